// round 10
// baseline (speedup 1.0000x reference)
#include <cuda_runtime.h>
#include <cuda_bf16.h>
#include <math.h>
typedef unsigned long long ull;
typedef __nv_bfloat16 bf16;

#define VOCAB 10000
#define VPAD  10048
#define H 1024
#define H2 2048
#define BB 32
#define TT 128
#define MROWS (BB*TT)
#define NB 128
#define NTHR 512

// recurrence smem float offsets
#define OA    0
#define OA1   16640
#define OWW   33280
#define ORED  49920
#define SMF   54016

// hgemm smem (bytes)
#define HA_L 18432
#define HB_H 36864
#define HB_L 46080
#define HBUF 55296
#define HSM  (2*HBUF)

// ---------------- device scratch ----------------
__device__ __align__(16) float g_gx0[(size_t)TT*BB*H2];
__device__ __align__(16) float g_cx0[(size_t)TT*BB*H];
__device__ __align__(16) float g_outT[(size_t)TT*BB*H];
__device__ __align__(16) float g_h0m[2][BB*H];
__device__ __align__(16) float g_h1m[BB*H];
__device__ __align__(16) float g_rh0m[BB*H];
__device__ __align__(16) float g_rh1m[BB*H];
__device__ __align__(16) float g_u0m[BB*H];
__device__ __align__(16) float g_u1m[BB*H];
__device__ __align__(16) float g_Tg0[(size_t)H2*H];
__device__ __align__(16) float g_Tg1[(size_t)H2*H2];
__device__ __align__(16) float g_Tc0[(size_t)H*H];
__device__ __align__(16) float g_Tc1[(size_t)H*H2];
__device__ __align__(16) bf16 g_xh[(size_t)MROWS*H], g_xl[(size_t)MROWS*H];
__device__ __align__(16) bf16 g_oh[(size_t)MROWS*H], g_ol[(size_t)MROWS*H];
__device__ __align__(16) bf16 g_wgh[(size_t)H2*H],  g_wgl[(size_t)H2*H];
__device__ __align__(16) bf16 g_wch[(size_t)H*H],   g_wcl[(size_t)H*H];
__device__ __align__(16) bf16 g_eh[(size_t)VPAD*H], g_el[(size_t)VPAD*H];
__device__ volatile unsigned g_cnt;
__device__ volatile unsigned g_gen;

// ---------------- helpers ----------------
__device__ __forceinline__ ull f2fma(ull a,ull x,ull y){ ull d; asm("fma.rn.f32x2 %0,%1,%2,%3;":"=l"(d):"l"(x),"l"(y),"l"(a)); return d; }
__device__ __forceinline__ float plo(ull v){ return __uint_as_float((unsigned)v); }
__device__ __forceinline__ float phi(ull v){ return __uint_as_float((unsigned)(v>>32)); }
__device__ __forceinline__ float sigf(float x){ return __fdividef(1.f, 1.f+__expf(-x)); }
__device__ __forceinline__ float tanhx(float x){ return 1.f-__fdividef(2.f, __expf(2.f*x)+1.f); }

__device__ __forceinline__ void cp16(void* d, const void* s){
    unsigned ds = (unsigned)__cvta_generic_to_shared(d);
    asm volatile("cp.async.cg.shared.global [%0], [%1], 16;" :: "r"(ds), "l"(s) : "memory");
}
#define CP_COMMIT asm volatile("cp.async.commit_group;" ::: "memory")
#define CP_WAIT0  asm volatile("cp.async.wait_group 0;" ::: "memory")

__device__ __forceinline__ void gsync(){
    __threadfence();
    __syncthreads();
    if (threadIdx.x == 0){
        unsigned gen = g_gen;
        unsigned old = atomicAdd((unsigned*)&g_cnt, 1u);
        if (old == NB-1){ g_cnt = 0; __threadfence(); g_gen = gen+1; }
        else { while (g_gen == gen) { __nanosleep(40); } }
    }
    __syncthreads();
}

// ---------------- HMMA primitives ----------------
__device__ __forceinline__ void ldm4(unsigned& r0, unsigned& r1, unsigned& r2, unsigned& r3,
                                     unsigned addr){
    asm volatile("ldmatrix.sync.aligned.m8n8.x4.shared.b16 {%0,%1,%2,%3}, [%4];"
        : "=r"(r0), "=r"(r1), "=r"(r2), "=r"(r3) : "r"(addr));
}
__device__ __forceinline__ void mma16816(float* c, const unsigned* a, const unsigned* b){
    asm volatile("mma.sync.aligned.m16n8k16.row.col.f32.bf16.bf16.f32 "
        "{%0,%1,%2,%3},{%4,%5,%6,%7},{%8,%9},{%0,%1,%2,%3};"
        : "+f"(c[0]), "+f"(c[1]), "+f"(c[2]), "+f"(c[3])
        : "r"(a[0]), "r"(a[1]), "r"(a[2]), "r"(a[3]), "r"(b[0]), "r"(b[1]));
}

// ---------------- fused prep kernels ----------------
// 1) all 4 fp32 weight transposes: dst[n][k] = src[srow0+k][n]
__global__ void prep_tr(const float* __restrict__ Wg0, const float* __restrict__ Wg1,
                        const float* __restrict__ Wc0, const float* __restrict__ Wc1,
                        float* __restrict__ Tg0, float* __restrict__ Tg1,
                        float* __restrict__ Tc0, float* __restrict__ Tc1){
    __shared__ float s[32][33];
    int b = blockIdx.x;
    const float* src; float* dst; int srow0, ld, ldd, bx, by;
    if (b < 2048){        src=Wg0; srow0=1024; ld=H2; dst=Tg0; ldd=H;  bx=b&31;            by=b>>5; }
    else if (b < 6144){   int q=b-2048; src=Wg1; srow0=0; ld=H2; dst=Tg1; ldd=H2; bx=q&63; by=q>>6; }
    else if (b < 7168){   int q=b-6144; src=Wc0; srow0=1024; ld=H; dst=Tc0; ldd=H; bx=q&31; by=q>>5; }
    else {                int q=b-7168; src=Wc1; srow0=0; ld=H; dst=Tc1; ldd=H2; bx=q&63;  by=q>>6; }
    int kb = bx*32, nb = by*32;
    int t = threadIdx.x, tx = t&31, ty = t>>5;
#pragma unroll
    for (int i=0;i<32;i+=8) s[ty+i][tx] = src[(size_t)(srow0+kb+ty+i)*ld + nb+tx];
    __syncthreads();
#pragma unroll
    for (int i=0;i<32;i+=8) dst[(size_t)(nb+ty+i)*ldd + kb+tx] = s[tx][ty+i];
}

// 2) all bf16 conversions: embed split, weight splits, padded embedding split
__global__ void prep_cv(const int* __restrict__ idx, const float* __restrict__ emb,
                        const float* __restrict__ Wg0, const float* __restrict__ Wc0,
                        bf16* __restrict__ xh, bf16* __restrict__ xl,
                        bf16* __restrict__ wgh, bf16* __restrict__ wgl,
                        bf16* __restrict__ wch, bf16* __restrict__ wcl,
                        bf16* __restrict__ eh,  bf16* __restrict__ el){
    __shared__ float s[32][33];
    int b = blockIdx.x, t = threadIdx.x;
    if (b < 4096){
        float4 v = ((const float4*)(emb + (size_t)idx[b]*H))[t];
        float a[4] = {v.x,v.y,v.z,v.w};
        size_t o = (size_t)b*H + t*4;
#pragma unroll
        for (int j=0;j<4;j++){
            bf16 h = __float2bfloat16(a[j]);
            xh[o+j] = h;
            xl[o+j] = __float2bfloat16(a[j] - __bfloat162float(h));
        }
    } else if (b < 7168){
        const float* src; bf16 *hi, *lo; int ld, kb, nb;
        if (b < 6144){ int q=b-4096; src=Wg0; ld=H2; hi=wgh; lo=wgl; kb=(q&31)*32; nb=(q>>5)*32; }
        else         { int q=b-6144; src=Wc0; ld=H;  hi=wch; lo=wcl; kb=(q&31)*32; nb=(q>>5)*32; }
        int tx = t&31, ty = t>>5;
#pragma unroll
        for (int i=0;i<32;i+=8) s[ty+i][tx] = src[(size_t)(kb+ty+i)*ld + nb+tx];
        __syncthreads();
#pragma unroll
        for (int i=0;i<32;i+=8){
            float v = s[tx][ty+i];
            bf16 h = __float2bfloat16(v);
            size_t o = (size_t)(nb+ty+i)*H + kb+tx;
            hi[o] = h;
            lo[o] = __float2bfloat16(v - __bfloat162float(h));
        }
    } else {
        int row = b - 7168;
        size_t o = (size_t)row*H + t*4;
        if (row < VOCAB){
            float4 v = ((const float4*)(emb + (size_t)row*H))[t];
            float a[4] = {v.x,v.y,v.z,v.w};
#pragma unroll
            for (int j=0;j<4;j++){
                bf16 h = __float2bfloat16(a[j]);
                eh[o+j] = h;
                el[o+j] = __float2bfloat16(a[j] - __bfloat162float(h));
            }
        } else {
#pragma unroll
            for (int j=0;j<4;j++){ eh[o+j] = __float2bfloat16(0.f); el[o+j] = __float2bfloat16(0.f); }
        }
    }
}

__global__ void outconv(const float* __restrict__ outT, bf16* __restrict__ oh, bf16* __restrict__ ol){
    int r = blockIdx.x, tid = threadIdx.x;
    int m = r>>7, t = r&127;
    float4 v = ((const float4*)(outT + ((size_t)t*BB + m)*H))[tid];
    float a[4] = {v.x,v.y,v.z,v.w};
    size_t o = (size_t)r*H + tid*4;
#pragma unroll
    for (int j=0;j<4;j++){
        bf16 h = __float2bfloat16(a[j]);
        oh[o+j] = h;
        ol[o+j] = __float2bfloat16(a[j] - __bfloat162float(h));
    }
}

// ---------------- HMMA bf16-split GEMM (r9, unchanged) ----------------
template<bool GRUL>
__global__ void __launch_bounds__(256, 1)
hgemm(const bf16* __restrict__ Ah, const bf16* __restrict__ Al,
      const bf16* __restrict__ Bh, const bf16* __restrict__ Bl,
      const float* __restrict__ bias, float* __restrict__ C, int N)
{
    extern __shared__ __align__(16) char smc[];
    const int tid = threadIdx.x, wid = tid>>5, lane = tid&31;
    const int n0 = blockIdx.x*64, m0 = blockIdx.y*128;
    const int wm = wid&3, wn = wid>>2;
    unsigned sb = (unsigned)__cvta_generic_to_shared(smc);

    auto stage = [&](int kc){
        char* base = smc + (kc&1)*HBUF;
#pragma unroll
        for (int u=0;u<8;u++){
            int e = tid + u*256;
            int pl = e>>10, i = e&1023, row = i>>3, g = i&7;
            const bf16* src = (pl?Al:Ah) + (size_t)(m0+row)*H + kc*64 + g*8;
            cp16(base + (pl?HA_L:0) + row*144 + g*16, src);
        }
#pragma unroll
        for (int u=0;u<4;u++){
            int e = tid + u*256;
            int pl = e>>9, i = e&511, row = i>>3, g = i&7;
            const bf16* src = (pl?Bl:Bh) + (size_t)(n0+row)*H + kc*64 + g*8;
            cp16(base + (pl?HB_L:HB_H) + row*144 + g*16, src);
        }
    };

    float cc[2][4][4];
#pragma unroll
    for (int a=0;a<2;a++)
#pragma unroll
        for (int b=0;b<4;b++)
#pragma unroll
            for (int q=0;q<4;q++) cc[a][b][q] = 0.f;

    stage(0); CP_COMMIT;
    for (int kc=0;kc<16;kc++){
        if (kc < 15){ stage(kc+1); CP_COMMIT;
            asm volatile("cp.async.wait_group 1;" ::: "memory");
        } else CP_WAIT0;
        __syncthreads();
        unsigned bufb = sb + (kc&1)*HBUF;
        unsigned aB = bufb + (wm*32 + (lane&15))*144 + ((lane>>4)&1)*16;
        unsigned bB = bufb + HB_H + (wn*32 + (lane&7) + ((lane>>4)&1)*8)*144 + ((lane>>3)&1)*16;
#pragma unroll
        for (int ks=0;ks<4;ks++){
            unsigned ah[8], al[8], bh[8], bl[8];
            ldm4(ah[0],ah[1],ah[2],ah[3], aB + ks*32);
            ldm4(ah[4],ah[5],ah[6],ah[7], aB + 16*144 + ks*32);
            ldm4(al[0],al[1],al[2],al[3], aB + HA_L + ks*32);
            ldm4(al[4],al[5],al[6],al[7], aB + HA_L + 16*144 + ks*32);
            ldm4(bh[0],bh[1],bh[2],bh[3], bB + ks*32);
            ldm4(bh[4],bh[5],bh[6],bh[7], bB + 16*144 + ks*32);
            ldm4(bl[0],bl[1],bl[2],bl[3], bB + (HB_L-HB_H) + ks*32);
            ldm4(bl[4],bl[5],bl[6],bl[7], bB + (HB_L-HB_H) + 16*144 + ks*32);
#pragma unroll
            for (int fm=0;fm<2;fm++)
#pragma unroll
                for (int fn=0;fn<4;fn++){
                    mma16816(cc[fm][fn], ah+fm*4, bh+fn*2);
                    mma16816(cc[fm][fn], ah+fm*4, bl+fn*2);
                    mma16816(cc[fm][fn], al+fm*4, bh+fn*2);
                }
        }
        __syncthreads();
    }

    const int rb = lane>>2, cb = (lane&3)*2;
#pragma unroll
    for (int fm=0;fm<2;fm++){
#pragma unroll
        for (int half=0;half<2;half++){
            int r = m0 + wm*32 + fm*16 + rb + half*8;
            int r2 = GRUL ? ((r & 127)*BB + (r >> 7)) : r;
            float* crow = C + (size_t)r2*N;
#pragma unroll
            for (int fn=0;fn<4;fn++){
                int n = n0 + wn*32 + fn*8 + cb;
                if (n < N){
                    float2 v;
                    v.x = cc[fm][fn][half*2+0];
                    v.y = cc[fm][fn][half*2+1];
                    if (bias){
                        float2 b = *(const float2*)(bias + n);
                        v.x += b.x; v.y += b.y;
                    }
                    *(float2*)(crow + n) = v;
                }
            }
        }
    }
}

// ---------------- persistent recurrence (single-sync chunk loops) ----------------
__global__ void __launch_bounds__(NTHR, 1)
rnn_persist(const float* __restrict__ bg0, const float* __restrict__ bc0,
            const float* __restrict__ bg1, const float* __restrict__ bc1)
{
    extern __shared__ __align__(16) float sm[];
    const int tid = threadIdx.x, c = blockIdx.x;
    const int lane = tid & 31, w = tid >> 5;

    for (int i = c*NTHR+tid; i < BB*H; i += NB*NTHR){ g_h0m[0][i]=0.f; g_h1m[i]=0.f; }
    gsync();

    const int tnA = w & 3, ksA = w >> 2;
    const bool aL0 = tnA < 2;
    const int tnB = w & 1, ksB = w >> 1;
    const bool bL0 = (tnB == 0);

    float* red = sm + ORED;
    int cur = 0;

    for (int t = 0; t <= TT; t++){
        const bool do0 = (t < TT), do1 = (t > 0);
        const float* __restrict__ h0c = g_h0m[cur];
        float* __restrict__ h0p = g_h0m[cur^1];
        const int nc = do1 ? 8 : 4;

        // PHASE A: gates
        {
            auto stage = [&](int kc){
                float* Ab = sm + OA + (kc&1)*8320;
                const float* src = (kc<4) ? h0c + kc*256 : g_h1m + (kc-4)*256;
                #pragma unroll
                for (int u=0;u<4;u++){ int f = tid+u*NTHR; int m = f>>6, kq = f&63;
                    cp16(Ab + m*260 + kq*4, src + m*H + kq*4); }
                float* Wb = sm + OWW + (kc&1)*8320;
                if (kc < 4){
                    #pragma unroll
                    for (int u=0;u<4;u++){ int f = tid+u*NTHR; int r = f>>6, kq = f&63;
                        const float* ws = (r<16) ? g_Tg0 + (size_t)(c*16+r)*H + kc*256
                                                 : g_Tg1 + (size_t)(c*16+r-16)*H2 + kc*256;
                        cp16(Wb + r*260 + kq*4, ws + kq*4); }
                } else {
                    #pragma unroll
                    for (int u=0;u<2;u++){ int f = tid+u*NTHR; int r = 16+(f>>6), kq = f&63;
                        cp16(Wb + r*260 + kq*4,
                             g_Tg1 + (size_t)(c*16+r-16)*H2 + kc*256 + kq*4); }
                }
            };
            stage(0); CP_COMMIT;
            ull acc[8];
            #pragma unroll
            for (int j=0;j<8;j++) acc[j] = 0ull;
            for (int kc=0;kc<nc;kc++){
                CP_WAIT0;
                __syncthreads();
                if (kc+1 < nc){ stage(kc+1); CP_COMMIT; }
                const bool act = aL0 ? (do0 && kc < 4) : do1;
                if (act){
                    const float* Ap = sm + OA + (kc&1)*8320 + lane*260 + ksA*64;
                    const float* Wp = sm + OWW + (kc&1)*8320 + (tnA*8)*260 + ksA*64;
                    #pragma unroll
                    for (int i=0;i<16;i++){
                        ulonglong2 a = *(const ulonglong2*)(Ap + i*4);
                        #pragma unroll
                        for (int j=0;j<8;j++){
                            ulonglong2 wv = *(const ulonglong2*)(Wp + j*260 + i*4);
                            acc[j] = f2fma(f2fma(acc[j], a.x, wv.x), a.y, wv.y);
                        }
                    }
                }
            }
            __syncthreads();
            #pragma unroll
            for (int j=0;j<8;j++)
                red[((tnA*8+j)*4 + ksA)*32 + lane] = plo(acc[j]) + phi(acc[j]);
            __syncthreads();
            #pragma unroll
            for (int q=0;q<2;q++){
                int o = tid*2+q, col = o>>5, m = o&31;
                const float* rp = red + col*128 + m;
                float s = rp[0] + rp[32] + rp[64] + rp[96];
                if (col < 16){
                    if (do0){
                        int n = c*16 + col;
                        s += g_gx0[((size_t)t*BB+m)*H2 + n] + bg0[n];
                        float g = sigf(s);
                        if (n < H) g_rh0m[m*H+n] = g * h0c[m*H+n];
                        else       g_u0m[m*H + n-H] = g;
                    }
                } else {
                    if (do1){
                        int n = c*16 + col - 16;
                        s += bg1[n];
                        float g = sigf(s);
                        if (n < H) g_rh1m[m*H+n] = g * g_h1m[m*H+n];
                        else       g_u1m[m*H + n-H] = g;
                    }
                }
            }
        }
        gsync();

        // PHASE B: candidates + update
        {
            auto stage = [&](int kc){
                if (kc < 4){
                    float* A0b = sm + OA + (kc&1)*8320;
                    const float* s0 = g_rh0m + kc*256;
                    #pragma unroll
                    for (int u=0;u<4;u++){ int f = tid+u*NTHR; int m = f>>6, kq = f&63;
                        cp16(A0b + m*260 + kq*4, s0 + m*H + kq*4); }
                }
                float* A1b = sm + OA1 + (kc&1)*8320;
                const float* s1 = (kc<4) ? h0c + kc*256 : g_rh1m + (kc-4)*256;
                #pragma unroll
                for (int u=0;u<4;u++){ int f = tid+u*NTHR; int m = f>>6, kq = f&63;
                    cp16(A1b + m*260 + kq*4, s1 + m*H + kq*4); }
                float* Wb = sm + OWW + (kc&1)*4160;
                if (kc < 4){
                    #pragma unroll
                    for (int u=0;u<2;u++){ int f = tid+u*NTHR; int r = f>>6, kq = f&63;
                        const float* ws = (r<8) ? g_Tc0 + (size_t)(c*8+r)*H + kc*256
                                                : g_Tc1 + (size_t)(c*8+r-8)*H2 + kc*256;
                        cp16(Wb + r*260 + kq*4, ws + kq*4); }
                } else {
                    int r = 8+(tid>>6), kq = tid&63;
                    cp16(Wb + r*260 + kq*4,
                         g_Tc1 + (size_t)(c*8+r-8)*H2 + kc*256 + kq*4);
                }
            };
            stage(0); CP_COMMIT;
            ull acc[8];
            #pragma unroll
            for (int j=0;j<8;j++) acc[j] = 0ull;
            for (int kc=0;kc<nc;kc++){
                CP_WAIT0;
                __syncthreads();
                if (kc+1 < nc){ stage(kc+1); CP_COMMIT; }
                const bool act = bL0 ? (do0 && kc < 4) : do1;
                if (act){
                    const float* Ap = sm + (bL0 ? OA : OA1) + (kc&1)*8320 + lane*260 + ksB*32;
                    const float* Wp = sm + OWW + (kc&1)*4160 + (tnB*8)*260 + ksB*32;
                    #pragma unroll
                    for (int i=0;i<8;i++){
                        ulonglong2 a = *(const ulonglong2*)(Ap + i*4);
                        #pragma unroll
                        for (int j=0;j<8;j++){
                            ulonglong2 wv = *(const ulonglong2*)(Wp + j*260 + i*4);
                            acc[j] = f2fma(f2fma(acc[j], a.x, wv.x), a.y, wv.y);
                        }
                    }
                }
            }
            __syncthreads();
            #pragma unroll
            for (int j=0;j<8;j++)
                red[((tnB*8+j)*8 + ksB)*32 + lane] = plo(acc[j]) + phi(acc[j]);
            __syncthreads();
            {
                int col = tid>>5, m = tid&31;
                const float* rp = red + col*256 + m;
                float s = rp[0]+rp[32]+rp[64]+rp[96]+rp[128]+rp[160]+rp[192]+rp[224];
                if (col < 8){
                    if (do0){
                        int n = c*8 + col;
                        s += g_cx0[((size_t)t*BB+m)*H + n] + bc0[n];
                        float cc2 = tanhx(s);
                        float u = g_u0m[m*H+n];
                        h0p[m*H+n] = u*h0c[m*H+n] + (1.f-u)*cc2;
                    }
                } else {
                    if (do1){
                        int n = c*8 + col - 8;
                        s += bc1[n];
                        float cc2 = tanhx(s);
                        float u = g_u1m[m*H+n];
                        float hn = u*g_h1m[m*H+n] + (1.f-u)*cc2;
                        g_h1m[m*H+n] = hn;
                        g_outT[((size_t)(t-1)*BB+m)*H + n] = hn;
                    }
                }
            }
        }
        cur ^= 1;
        gsync();
    }
}

// ---------------- launch ----------------
extern "C" void kernel_launch(void* const* d_in, const int* in_sizes, int n_in,
                              void* d_out, int out_size)
{
    const int*   idx = (const int*)  d_in[0];
    const float* emb = (const float*)d_in[1];
    const float* Wg0 = (const float*)d_in[2];
    const float* bg0 = (const float*)d_in[3];
    const float* Wc0 = (const float*)d_in[4];
    const float* bc0 = (const float*)d_in[5];
    const float* Wg1 = (const float*)d_in[6];
    const float* bg1 = (const float*)d_in[7];
    const float* Wc1 = (const float*)d_in[8];
    const float* bc1 = (const float*)d_in[9];
    const float* smb = (const float*)d_in[10];
    float* out = (float*)d_out;

    float *pgx0,*pcx0,*poutT,*pTg0,*pTg1,*pTc0,*pTc1;
    bf16 *pxh,*pxl,*poh,*pol,*pwgh,*pwgl,*pwch,*pwcl,*peh,*pel;
    cudaGetSymbolAddress((void**)&pgx0,  g_gx0);
    cudaGetSymbolAddress((void**)&pcx0,  g_cx0);
    cudaGetSymbolAddress((void**)&poutT, g_outT);
    cudaGetSymbolAddress((void**)&pTg0,  g_Tg0);
    cudaGetSymbolAddress((void**)&pTg1,  g_Tg1);
    cudaGetSymbolAddress((void**)&pTc0,  g_Tc0);
    cudaGetSymbolAddress((void**)&pTc1,  g_Tc1);
    cudaGetSymbolAddress((void**)&pxh,   g_xh);
    cudaGetSymbolAddress((void**)&pxl,   g_xl);
    cudaGetSymbolAddress((void**)&poh,   g_oh);
    cudaGetSymbolAddress((void**)&pol,   g_ol);
    cudaGetSymbolAddress((void**)&pwgh,  g_wgh);
    cudaGetSymbolAddress((void**)&pwgl,  g_wgl);
    cudaGetSymbolAddress((void**)&pwch,  g_wch);
    cudaGetSymbolAddress((void**)&pwcl,  g_wcl);
    cudaGetSymbolAddress((void**)&peh,   g_eh);
    cudaGetSymbolAddress((void**)&pel,   g_el);

    static bool attr_set = false;
    if (!attr_set){
        cudaFuncSetAttribute(rnn_persist, cudaFuncAttributeMaxDynamicSharedMemorySize, SMF*4);
        cudaFuncSetAttribute(hgemm<true>,  cudaFuncAttributeMaxDynamicSharedMemorySize, HSM);
        cudaFuncSetAttribute(hgemm<false>, cudaFuncAttributeMaxDynamicSharedMemorySize, HSM);
        attr_set = true;
    }

    // fused prep: transposes, then all bf16 conversions
    prep_tr<<<9216, 256>>>(Wg0, Wg1, Wc0, Wc1, pTg0, pTg1, pTc0, pTc1);
    prep_cv<<<7168 + VPAD, 256>>>(idx, emb, Wg0, Wc0, pxh, pxl, pwgh, pwgl, pwch, pwcl, peh, pel);

    // layer-0 x-projections on tensor cores -> [t][m][n]
    hgemm<true><<<dim3(H2/64, MROWS/128), 256, HSM>>>(pxh, pxl, pwgh, pwgl, nullptr, pgx0, H2);
    hgemm<true><<<dim3(H/64,  MROWS/128), 256, HSM>>>(pxh, pxl, pwch, pwcl, nullptr, pcx0, H);

    // recurrence (fp32 persistent kernel)
    rnn_persist<<<NB, NTHR, SMF*4>>>(bg0, bc0, bg1, bc1);

    // logits on tensor cores
    outconv<<<MROWS, 256>>>(poutT, poh, pol);
    hgemm<false><<<dim3(VPAD/64, MROWS/128), 256, HSM>>>(poh, pol, peh, pel, smb, out, VOCAB);
}

// round 11
// speedup vs baseline: 1.2811x; 1.2811x over previous
#include <cuda_runtime.h>
#include <cuda_bf16.h>
#include <math.h>
typedef unsigned long long ull;
typedef __nv_bfloat16 bf16;

#define VOCAB 10000
#define VPAD  10048
#define H 1024
#define H2 2048
#define BB 32
#define TT 128
#define MROWS (BB*TT)
#define NB 128
#define NTHR 256

// rnn smem layout (bytes): buffers of 17408 (hi 32x272=8704, lo +8704)
#define SA   0
#define SA1  34816
#define SW   69632
#define SRED 104448
#define RSM  112640

// hgemm smem (bytes)
#define HA_L 18432
#define HB_H 36864
#define HB_L 46080
#define HBUF 55296
#define HSM  (2*HBUF)

// ---------------- device scratch ----------------
__device__ __align__(16) float g_gx0[(size_t)TT*BB*H2];   // [t][m][n]
__device__ __align__(16) float g_cx0[(size_t)TT*BB*H];
__device__ __align__(16) float g_outT[(size_t)TT*BB*H];
__device__ __align__(16) float g_h0m[2][BB*H];
__device__ __align__(16) float g_h1m[BB*H];
__device__ __align__(16) float g_u0m[BB*H];
__device__ __align__(16) float g_u1m[BB*H];
// bf16 state planes (A operands), m-major [m][k]
__device__ __align__(16) bf16 g_h0h[2][BB*H], g_h0l[2][BB*H];
__device__ __align__(16) bf16 g_h1h[BB*H],  g_h1l[BB*H];
__device__ __align__(16) bf16 g_rh0h[BB*H], g_rh0l[BB*H];
__device__ __align__(16) bf16 g_rh1h[BB*H], g_rh1l[BB*H];
// bf16 recurrent weight planes, [n][k]
__device__ __align__(16) bf16 g_wgt0h[(size_t)H2*H],  g_wgt0l[(size_t)H2*H];
__device__ __align__(16) bf16 g_wgt1h[(size_t)H2*H2], g_wgt1l[(size_t)H2*H2];
__device__ __align__(16) bf16 g_wct0h[(size_t)H*H],   g_wct0l[(size_t)H*H];
__device__ __align__(16) bf16 g_wct1h[(size_t)H*H2],  g_wct1l[(size_t)H*H2];
// hgemm planes
__device__ __align__(16) bf16 g_xh[(size_t)MROWS*H], g_xl[(size_t)MROWS*H];
__device__ __align__(16) bf16 g_oh[(size_t)MROWS*H], g_ol[(size_t)MROWS*H];
__device__ __align__(16) bf16 g_wgh[(size_t)H2*H],  g_wgl[(size_t)H2*H];
__device__ __align__(16) bf16 g_wch[(size_t)H*H],   g_wcl[(size_t)H*H];
__device__ __align__(16) bf16 g_eh[(size_t)VPAD*H], g_el[(size_t)VPAD*H];
__device__ volatile unsigned g_cnt;
__device__ volatile unsigned g_gen;

// ---------------- helpers ----------------
__device__ __forceinline__ float sigf(float x){ return __fdividef(1.f, 1.f+__expf(-x)); }
__device__ __forceinline__ float tanhx(float x){ return 1.f-__fdividef(2.f, __expf(2.f*x)+1.f); }

__device__ __forceinline__ void cp16(void* d, const void* s){
    unsigned ds = (unsigned)__cvta_generic_to_shared(d);
    asm volatile("cp.async.cg.shared.global [%0], [%1], 16;" :: "r"(ds), "l"(s) : "memory");
}
#define CP_COMMIT asm volatile("cp.async.commit_group;" ::: "memory")
#define CP_WAIT0  asm volatile("cp.async.wait_group 0;" ::: "memory")

__device__ __forceinline__ void gsync(){
    __threadfence();
    __syncthreads();
    if (threadIdx.x == 0){
        unsigned gen = g_gen;
        unsigned old = atomicAdd((unsigned*)&g_cnt, 1u);
        if (old == NB-1){ g_cnt = 0; __threadfence(); g_gen = gen+1; }
        else { while (g_gen == gen) { __nanosleep(40); } }
    }
    __syncthreads();
}

__device__ __forceinline__ void ldm4(unsigned& r0, unsigned& r1, unsigned& r2, unsigned& r3,
                                     unsigned addr){
    asm volatile("ldmatrix.sync.aligned.m8n8.x4.shared.b16 {%0,%1,%2,%3}, [%4];"
        : "=r"(r0), "=r"(r1), "=r"(r2), "=r"(r3) : "r"(addr));
}
__device__ __forceinline__ void mma16816(float* c, const unsigned* a, const unsigned* b){
    asm volatile("mma.sync.aligned.m16n8k16.row.col.f32.bf16.bf16.f32 "
        "{%0,%1,%2,%3},{%4,%5,%6,%7},{%8,%9},{%0,%1,%2,%3};"
        : "+f"(c[0]), "+f"(c[1]), "+f"(c[2]), "+f"(c[3])
        : "r"(a[0]), "r"(a[1]), "r"(a[2]), "r"(a[3]), "r"(b[0]), "r"(b[1]));
}
__device__ __forceinline__ void wsplit(float v, bf16* hp, bf16* lp, size_t o){
    bf16 h = __float2bfloat16(v);
    hp[o] = h; lp[o] = __float2bfloat16(v - __bfloat162float(h));
}

// ---------------- prep kernels ----------------
// recurrent weights -> transposed bf16 planes [n][k]
__global__ void prep_wq(const float* __restrict__ Wg0, const float* __restrict__ Wg1,
                        const float* __restrict__ Wc0, const float* __restrict__ Wc1){
    __shared__ float s[32][33];
    int b = blockIdx.x;
    const float* src; bf16 *dh, *dl; int srow0, ld, ldd, bx, by;
    if (b < 2048){      src=Wg0; srow0=1024; ld=H2; dh=g_wgt0h; dl=g_wgt0l; ldd=H;  bx=b&31; by=b>>5; }
    else if (b<6144){ int q=b-2048; src=Wg1; srow0=0; ld=H2; dh=g_wgt1h; dl=g_wgt1l; ldd=H2; bx=q&63; by=q>>6; }
    else if (b<7168){ int q=b-6144; src=Wc0; srow0=1024; ld=H; dh=g_wct0h; dl=g_wct0l; ldd=H; bx=q&31; by=q>>5; }
    else {            int q=b-7168; src=Wc1; srow0=0; ld=H; dh=g_wct1h; dl=g_wct1l; ldd=H2; bx=q&63; by=q>>6; }
    int kb = bx*32, nb = by*32;
    int t = threadIdx.x, tx = t&31, ty = t>>5;
#pragma unroll
    for (int i=0;i<32;i+=8) s[ty+i][tx] = src[(size_t)(srow0+kb+ty+i)*ld + nb+tx];
    __syncthreads();
#pragma unroll
    for (int i=0;i<32;i+=8)
        wsplit(s[tx][ty+i], dh, dl, (size_t)(nb+ty+i)*ldd + kb+tx);
}

// bf16 conversions for hgemm: x embed split, x-proj weight splits, padded emb split
__global__ void prep_cv(const int* __restrict__ idx, const float* __restrict__ emb,
                        const float* __restrict__ Wg0, const float* __restrict__ Wc0){
    __shared__ float s[32][33];
    int b = blockIdx.x, t = threadIdx.x;
    if (b < 4096){
        float4 v = ((const float4*)(emb + (size_t)idx[b]*H))[t];
        float a[4] = {v.x,v.y,v.z,v.w};
        size_t o = (size_t)b*H + t*4;
#pragma unroll
        for (int j=0;j<4;j++) wsplit(a[j], g_xh, g_xl, o+j);
    } else if (b < 7168){
        const float* src; bf16 *hi, *lo; int ld, kb, nb;
        if (b < 6144){ int q=b-4096; src=Wg0; ld=H2; hi=g_wgh; lo=g_wgl; kb=(q&31)*32; nb=(q>>5)*32; }
        else         { int q=b-6144; src=Wc0; ld=H;  hi=g_wch; lo=g_wcl; kb=(q&31)*32; nb=(q>>5)*32; }
        int tx = t&31, ty = t>>5;
#pragma unroll
        for (int i=0;i<32;i+=8) s[ty+i][tx] = src[(size_t)(kb+ty+i)*ld + nb+tx];
        __syncthreads();
#pragma unroll
        for (int i=0;i<32;i+=8)
            wsplit(s[tx][ty+i], hi, lo, (size_t)(nb+ty+i)*H + kb+tx);
    } else {
        int row = b - 7168;
        size_t o = (size_t)row*H + t*4;
        if (row < VOCAB){
            float4 v = ((const float4*)(emb + (size_t)row*H))[t];
            float a[4] = {v.x,v.y,v.z,v.w};
#pragma unroll
            for (int j=0;j<4;j++) wsplit(a[j], g_eh, g_el, o+j);
        } else {
#pragma unroll
            for (int j=0;j<4;j++){ g_eh[o+j]=__float2bfloat16(0.f); g_el[o+j]=__float2bfloat16(0.f); }
        }
    }
}

__global__ void outconv(const float* __restrict__ outT){
    int r = blockIdx.x, tid = threadIdx.x;
    int m = r>>7, t = r&127;
    float4 v = ((const float4*)(outT + ((size_t)t*BB + m)*H))[tid];
    float a[4] = {v.x,v.y,v.z,v.w};
    size_t o = (size_t)r*H + tid*4;
#pragma unroll
    for (int j=0;j<4;j++) wsplit(a[j], g_oh, g_ol, o+j);
}

// ---------------- HMMA bf16-split big GEMM (r9, proven) ----------------
template<bool GRUL>
__global__ void __launch_bounds__(256, 1)
hgemm(const bf16* __restrict__ Ah, const bf16* __restrict__ Al,
      const bf16* __restrict__ Bh, const bf16* __restrict__ Bl,
      const float* __restrict__ bias, float* __restrict__ C, int N)
{
    extern __shared__ __align__(16) char smc[];
    const int tid = threadIdx.x, wid = tid>>5, lane = tid&31;
    const int n0 = blockIdx.x*64, m0 = blockIdx.y*128;
    const int wm = wid&3, wn = wid>>2;
    unsigned sb = (unsigned)__cvta_generic_to_shared(smc);

    auto stage = [&](int kc){
        char* base = smc + (kc&1)*HBUF;
#pragma unroll
        for (int u=0;u<8;u++){
            int e = tid + u*256;
            int pl = e>>10, i = e&1023, row = i>>3, g = i&7;
            const bf16* src = (pl?Al:Ah) + (size_t)(m0+row)*H + kc*64 + g*8;
            cp16(base + (pl?HA_L:0) + row*144 + g*16, src);
        }
#pragma unroll
        for (int u=0;u<4;u++){
            int e = tid + u*256;
            int pl = e>>9, i = e&511, row = i>>3, g = i&7;
            const bf16* src = (pl?Bl:Bh) + (size_t)(n0+row)*H + kc*64 + g*8;
            cp16(base + (pl?HB_L:HB_H) + row*144 + g*16, src);
        }
    };

    float cc[2][4][4];
#pragma unroll
    for (int a=0;a<2;a++)
#pragma unroll
        for (int b=0;b<4;b++)
#pragma unroll
            for (int q=0;q<4;q++) cc[a][b][q] = 0.f;

    stage(0); CP_COMMIT;
    for (int kc=0;kc<16;kc++){
        if (kc < 15){ stage(kc+1); CP_COMMIT;
            asm volatile("cp.async.wait_group 1;" ::: "memory");
        } else CP_WAIT0;
        __syncthreads();
        unsigned bufb = sb + (kc&1)*HBUF;
        unsigned aB = bufb + (wm*32 + (lane&15))*144 + ((lane>>4)&1)*16;
        unsigned bB = bufb + HB_H + (wn*32 + (lane&7) + ((lane>>4)&1)*8)*144 + ((lane>>3)&1)*16;
#pragma unroll
        for (int ks=0;ks<4;ks++){
            unsigned ah[8], al[8], bh[8], bl[8];
            ldm4(ah[0],ah[1],ah[2],ah[3], aB + ks*32);
            ldm4(ah[4],ah[5],ah[6],ah[7], aB + 16*144 + ks*32);
            ldm4(al[0],al[1],al[2],al[3], aB + HA_L + ks*32);
            ldm4(al[4],al[5],al[6],al[7], aB + HA_L + 16*144 + ks*32);
            ldm4(bh[0],bh[1],bh[2],bh[3], bB + ks*32);
            ldm4(bh[4],bh[5],bh[6],bh[7], bB + 16*144 + ks*32);
            ldm4(bl[0],bl[1],bl[2],bl[3], bB + (HB_L-HB_H) + ks*32);
            ldm4(bl[4],bl[5],bl[6],bl[7], bB + (HB_L-HB_H) + 16*144 + ks*32);
#pragma unroll
            for (int fm=0;fm<2;fm++)
#pragma unroll
                for (int fn=0;fn<4;fn++){
                    mma16816(cc[fm][fn], ah+fm*4, bh+fn*2);
                    mma16816(cc[fm][fn], ah+fm*4, bl+fn*2);
                    mma16816(cc[fm][fn], al+fm*4, bh+fn*2);
                }
        }
        __syncthreads();
    }

    const int rb = lane>>2, cb = (lane&3)*2;
#pragma unroll
    for (int fm=0;fm<2;fm++){
#pragma unroll
        for (int half=0;half<2;half++){
            int r = m0 + wm*32 + fm*16 + rb + half*8;
            int r2 = GRUL ? ((r & 127)*BB + (r >> 7)) : r;
            float* crow = C + (size_t)r2*N;
#pragma unroll
            for (int fn=0;fn<4;fn++){
                int n = n0 + wn*32 + fn*8 + cb;
                if (n < N){
                    float2 v;
                    v.x = cc[fm][fn][half*2+0];
                    v.y = cc[fm][fn][half*2+1];
                    if (bias){
                        float2 b = *(const float2*)(bias + n);
                        v.x += b.x; v.y += b.y;
                    }
                    *(float2*)(crow + n) = v;
                }
            }
        }
    }
}

// ---------------- persistent HMMA recurrence ----------------
__global__ void __launch_bounds__(NTHR, 1)
rnn_persist(const float* __restrict__ bg0, const float* __restrict__ bc0,
            const float* __restrict__ bg1, const float* __restrict__ bc1)
{
    extern __shared__ __align__(16) char smc[];
    const int tid = threadIdx.x, c = blockIdx.x;
    const int lane = tid & 31, w = tid >> 5;
    unsigned sb = (unsigned)__cvta_generic_to_shared(smc);
    float* redf = (float*)(smc + SRED);

    {   int gt = c*NTHR + tid;
        bf16 z = __float2bfloat16(0.f);
        g_h0m[0][gt]=0.f; g_h1m[gt]=0.f;
        g_h0h[0][gt]=z; g_h0l[0][gt]=z; g_h1h[gt]=z; g_h1l[gt]=z;
    }
    gsync();

    // phase A warps: ng(4) n-groups of 8 cols (0,1=L0; 2,3=L1), ks(2) k-split
    const int ngA = w & 3, ksA = w >> 2;
    // phase B warps: l(2) layer, ks(4)
    const int lB = w & 1, ksB = w >> 1;

    int cur = 0;
    for (int t = 0; t <= TT; t++){
        const bool do0 = (t < TT), do1 = (t > 0);
        const int nc = do1 ? 16 : 8;

        // ===================== PHASE A: gates =====================
        {
            auto stage = [&](int kc){
                char* Ab = smc + SA + (kc&1)*17408;
                const bf16 *sh, *sl; int ko;
                if (kc < 8){ sh = g_h0h[cur]; sl = g_h0l[cur]; ko = kc*128; }
                else       { sh = g_h1h;      sl = g_h1l;      ko = (kc-8)*128; }
                #pragma unroll
                for (int u=0;u<2;u++){
                    int e = tid + u*NTHR; int row = e>>4, g = e&15;
                    cp16(Ab + row*272 + g*16,        sh + (size_t)row*H + ko + g*8);
                    cp16(Ab + 8704 + row*272 + g*16, sl + (size_t)row*H + ko + g*8);
                }
                char* Wb = smc + SW + (kc&1)*17408;
                {   int r = tid>>4, g = tid&15;     // 16 rows x 16 groups
                    size_t o1 = (size_t)(c*16 + r)*H2 + kc*128 + g*8;
                    cp16(Wb + (16+r)*272 + g*16,        g_wgt1h + o1);
                    cp16(Wb + 8704 + (16+r)*272 + g*16, g_wgt1l + o1);
                    if (kc < 8){
                        size_t o0 = (size_t)(c*16 + r)*H + kc*128 + g*8;
                        cp16(Wb + r*272 + g*16,        g_wgt0h + o0);
                        cp16(Wb + 8704 + r*272 + g*16, g_wgt0l + o0);
                    }
                }
            };
            stage(0); CP_COMMIT;
            float c0[2][4], c1[2][4], c2[2][4];
            #pragma unroll
            for (int fm=0;fm<2;fm++)
                #pragma unroll
                for (int q=0;q<4;q++){ c0[fm][q]=0.f; c1[fm][q]=0.f; c2[fm][q]=0.f; }

            for (int kc=0;kc<nc;kc++){
                CP_WAIT0;
                __syncthreads();
                if (kc+1 < nc){ stage(kc+1); CP_COMMIT; }
                const bool act = (ngA < 2) ? (do0 && kc < 8) : do1;
                if (act){
                    unsigned sA = sb + SA + (kc&1)*17408;
                    unsigned sW = sb + SW + (kc&1)*17408;
                    unsigned wB = sW + (ngA*8 + (lane&7))*272 + ((lane>>3)&3)*16 + ksA*128;
                    unsigned bh[8], bl[8];
                    ldm4(bh[0],bh[1],bh[2],bh[3], wB);
                    ldm4(bh[4],bh[5],bh[6],bh[7], wB + 64);
                    ldm4(bl[0],bl[1],bl[2],bl[3], wB + 8704);
                    ldm4(bl[4],bl[5],bl[6],bl[7], wB + 8704 + 64);
                    unsigned aB = sA + (lane&15)*272 + ((lane>>4)&1)*16 + ksA*128;
                    #pragma unroll
                    for (int s=0;s<4;s++){
                        unsigned a0[4], a1[4], l0[4], l1[4];
                        ldm4(a0[0],a0[1],a0[2],a0[3], aB + s*32);
                        ldm4(a1[0],a1[1],a1[2],a1[3], aB + 16*272 + s*32);
                        ldm4(l0[0],l0[1],l0[2],l0[3], aB + 8704 + s*32);
                        ldm4(l1[0],l1[1],l1[2],l1[3], aB + 8704 + 16*272 + s*32);
                        mma16816(c0[0], a0, bh+2*s); mma16816(c0[1], a1, bh+2*s);
                        mma16816(c1[0], a0, bl+2*s); mma16816(c1[1], a1, bl+2*s);
                        mma16816(c2[0], l0, bh+2*s); mma16816(c2[1], l1, bh+2*s);
                    }
                }
            }
            __syncthreads();
            #pragma unroll
            for (int fm=0;fm<2;fm++)
                #pragma unroll
                for (int q=0;q<4;q++){
                    int m = fm*16 + (lane>>2) + (q>>1)*8;
                    int nl = (lane&3)*2 + (q&1);
                    redf[((ksA*4+ngA)*32 + m)*8 + nl] = c0[fm][q]+c1[fm][q]+c2[fm][q];
                }
            __syncthreads();
            #pragma unroll
            for (int u=0;u<4;u++){
                int o = tid + u*NTHR;
                int m = o>>5, col = o&31;
                int ng2 = col>>3, nl = col&7;
                float s = redf[(ng2*32+m)*8+nl] + redf[((4+ng2)*32+m)*8+nl];
                if (col < 16){
                    if (do0){
                        int n = c*16 + col;
                        s += g_gx0[((size_t)t*BB+m)*H2 + n] + bg0[n];
                        float g = sigf(s);
                        if (n < H){
                            float v = g * g_h0m[cur][m*H+n];
                            wsplit(v, g_rh0h, g_rh0l, (size_t)m*H + n);
                        } else g_u0m[m*H + n-H] = g;
                    }
                } else {
                    if (do1){
                        int n = c*16 + col - 16;
                        s += bg1[n];
                        float g = sigf(s);
                        if (n < H){
                            float v = g * g_h1m[m*H+n];
                            wsplit(v, g_rh1h, g_rh1l, (size_t)m*H + n);
                        } else g_u1m[m*H + n-H] = g;
                    }
                }
            }
        }
        gsync();

        // ===================== PHASE B: candidates + update =====================
        {
            auto stage = [&](int kc){
                char* A1b = smc + SA1 + (kc&1)*17408;
                const bf16 *sh, *sl; int ko;
                if (kc < 8){ sh = g_h0h[cur]; sl = g_h0l[cur]; ko = kc*128; }
                else       { sh = g_rh1h;     sl = g_rh1l;     ko = (kc-8)*128; }
                #pragma unroll
                for (int u=0;u<2;u++){
                    int e = tid + u*NTHR; int row = e>>4, g = e&15;
                    cp16(A1b + row*272 + g*16,        sh + (size_t)row*H + ko + g*8);
                    cp16(A1b + 8704 + row*272 + g*16, sl + (size_t)row*H + ko + g*8);
                }
                if (kc < 8){
                    char* A0b = smc + SA + (kc&1)*17408;
                    #pragma unroll
                    for (int u=0;u<2;u++){
                        int e = tid + u*NTHR; int row = e>>4, g = e&15;
                        cp16(A0b + row*272 + g*16,        g_rh0h + (size_t)row*H + kc*128 + g*8);
                        cp16(A0b + 8704 + row*272 + g*16, g_rh0l + (size_t)row*H + kc*128 + g*8);
                    }
                }
                char* Wb = smc + SW + (kc&1)*17408;
                {   int pl = tid>>7, i = tid&127, r = i>>4, g = i&15;   // 8 rows each
                    size_t o1 = (size_t)(c*8 + r)*H2 + kc*128 + g*8;
                    cp16(Wb + pl*8704 + (8+r)*272 + g*16, (pl? g_wct1l : g_wct1h) + o1);
                    if (kc < 8){
                        size_t o0 = (size_t)(c*8 + r)*H + kc*128 + g*8;
                        cp16(Wb + pl*8704 + r*272 + g*16, (pl? g_wct0l : g_wct0h) + o0);
                    }
                }
            };
            stage(0); CP_COMMIT;
            float c0[2][4], c1[2][4], c2[2][4];
            #pragma unroll
            for (int fm=0;fm<2;fm++)
                #pragma unroll
                for (int q=0;q<4;q++){ c0[fm][q]=0.f; c1[fm][q]=0.f; c2[fm][q]=0.f; }

            for (int kc=0;kc<nc;kc++){
                CP_WAIT0;
                __syncthreads();
                if (kc+1 < nc){ stage(kc+1); CP_COMMIT; }
                const bool act = (lB == 0) ? (do0 && kc < 8) : do1;
                if (act){
                    unsigned sAx = sb + (lB ? SA1 : SA) + (kc&1)*17408;
                    unsigned sW = sb + SW + (kc&1)*17408;
                    unsigned wB = sW + (lB*8 + (lane&7))*272 + ((lane>>3)&3)*16 + ksB*64;
                    unsigned bh[4], bl[4];
                    ldm4(bh[0],bh[1],bh[2],bh[3], wB);
                    ldm4(bl[0],bl[1],bl[2],bl[3], wB + 8704);
                    unsigned aB = sAx + (lane&15)*272 + ((lane>>4)&1)*16 + ksB*64;
                    #pragma unroll
                    for (int s=0;s<2;s++){
                        unsigned a0[4], a1[4], l0[4], l1[4];
                        ldm4(a0[0],a0[1],a0[2],a0[3], aB + s*32);
                        ldm4(a1[0],a1[1],a1[2],a1[3], aB + 16*272 + s*32);
                        ldm4(l0[0],l0[1],l0[2],l0[3], aB + 8704 + s*32);
                        ldm4(l1[0],l1[1],l1[2],l1[3], aB + 8704 + 16*272 + s*32);
                        mma16816(c0[0], a0, bh+2*s); mma16816(c0[1], a1, bh+2*s);
                        mma16816(c1[0], a0, bl+2*s); mma16816(c1[1], a1, bl+2*s);
                        mma16816(c2[0], l0, bh+2*s); mma16816(c2[1], l1, bh+2*s);
                    }
                }
            }
            __syncthreads();
            #pragma unroll
            for (int fm=0;fm<2;fm++)
                #pragma unroll
                for (int q=0;q<4;q++){
                    int m = fm*16 + (lane>>2) + (q>>1)*8;
                    int nl = (lane&3)*2 + (q&1);
                    redf[((ksB*2+lB)*32 + m)*8 + nl] = c0[fm][q]+c1[fm][q]+c2[fm][q];
                }
            __syncthreads();
            #pragma unroll
            for (int u=0;u<2;u++){
                int o = tid + u*NTHR;
                int m = o>>4, col = o&15;
                int lg = col>>3, nl = col&7;
                float s = redf[((0*2+lg)*32+m)*8+nl] + redf[((1*2+lg)*32+m)*8+nl]
                        + redf[((2*2+lg)*32+m)*8+nl] + redf[((3*2+lg)*32+m)*8+nl];
                if (lg == 0){
                    if (do0){
                        int n = c*8 + nl;
                        s += g_cx0[((size_t)t*BB+m)*H + n] + bc0[n];
                        float cc = tanhx(s);
                        float uu = g_u0m[m*H+n];
                        float hn = uu * g_h0m[cur][m*H+n] + (1.f-uu)*cc;
                        g_h0m[cur^1][m*H+n] = hn;
                        wsplit(hn, g_h0h[cur^1], g_h0l[cur^1], (size_t)m*H + n);
                    }
                } else {
                    if (do1){
                        int n = c*8 + nl;
                        s += bc1[n];
                        float cc = tanhx(s);
                        float uu = g_u1m[m*H+n];
                        float hn = uu * g_h1m[m*H+n] + (1.f-uu)*cc;
                        g_h1m[m*H+n] = hn;
                        wsplit(hn, g_h1h, g_h1l, (size_t)m*H + n);
                        g_outT[((size_t)(t-1)*BB+m)*H + n] = hn;
                    }
                }
            }
        }
        cur ^= 1;
        gsync();
    }
}

// ---------------- launch ----------------
extern "C" void kernel_launch(void* const* d_in, const int* in_sizes, int n_in,
                              void* d_out, int out_size)
{
    const int*   idx = (const int*)  d_in[0];
    const float* emb = (const float*)d_in[1];
    const float* Wg0 = (const float*)d_in[2];
    const float* bg0 = (const float*)d_in[3];
    const float* Wc0 = (const float*)d_in[4];
    const float* bc0 = (const float*)d_in[5];
    const float* Wg1 = (const float*)d_in[6];
    const float* bg1 = (const float*)d_in[7];
    const float* Wc1 = (const float*)d_in[8];
    const float* bc1 = (const float*)d_in[9];
    const float* smb = (const float*)d_in[10];
    float* out = (float*)d_out;

    float *pgx0,*pcx0,*poutT;
    bf16 *pxh,*pxl,*poh,*pol,*pwgh,*pwgl,*pwch,*pwcl,*peh,*pel;
    cudaGetSymbolAddress((void**)&pgx0,  g_gx0);
    cudaGetSymbolAddress((void**)&pcx0,  g_cx0);
    cudaGetSymbolAddress((void**)&poutT, g_outT);
    cudaGetSymbolAddress((void**)&pxh,   g_xh);
    cudaGetSymbolAddress((void**)&pxl,   g_xl);
    cudaGetSymbolAddress((void**)&poh,   g_oh);
    cudaGetSymbolAddress((void**)&pol,   g_ol);
    cudaGetSymbolAddress((void**)&pwgh,  g_wgh);
    cudaGetSymbolAddress((void**)&pwgl,  g_wgl);
    cudaGetSymbolAddress((void**)&pwch,  g_wch);
    cudaGetSymbolAddress((void**)&pwcl,  g_wcl);
    cudaGetSymbolAddress((void**)&peh,   g_eh);
    cudaGetSymbolAddress((void**)&pel,   g_el);

    static bool attr_set = false;
    if (!attr_set){
        cudaFuncSetAttribute(rnn_persist, cudaFuncAttributeMaxDynamicSharedMemorySize, RSM);
        cudaFuncSetAttribute(hgemm<true>,  cudaFuncAttributeMaxDynamicSharedMemorySize, HSM);
        cudaFuncSetAttribute(hgemm<false>, cudaFuncAttributeMaxDynamicSharedMemorySize, HSM);
        attr_set = true;
    }

    // prep: recurrent weight planes + hgemm planes
    prep_wq<<<9216, 256>>>(Wg0, Wg1, Wc0, Wc1);
    prep_cv<<<7168 + VPAD, 256>>>(idx, emb, Wg0, Wc0);

    // layer-0 x-projections -> [t][m][n]
    hgemm<true><<<dim3(H2/64, MROWS/128), 256, HSM>>>(pxh, pxl, pwgh, pwgl, nullptr, pgx0, H2);
    hgemm<true><<<dim3(H/64,  MROWS/128), 256, HSM>>>(pxh, pxl, pwch, pwcl, nullptr, pcx0, H);

    // HMMA recurrence
    rnn_persist<<<NB, NTHR, RSM>>>(bg0, bc0, bg1, bc1);

    // logits
    outconv<<<MROWS, 256>>>(poutT);
    hgemm<false><<<dim3(VPAD/64, MROWS/128), 256, HSM>>>(poh, pol, peh, pel, smb, out, VOCAB);
}

// round 12
// speedup vs baseline: 1.3601x; 1.0617x over previous
#include <cuda_runtime.h>
#include <cuda_bf16.h>
#include <math.h>
typedef unsigned long long ull;
typedef __nv_bfloat16 bf16;

#define VOCAB 10000
#define VPAD  10048
#define H 1024
#define H2 2048
#define BB 32
#define TT 128
#define MROWS (BB*TT)
#define NB 128
#define NTHR 256

// rnn smem layout (bytes): 3-deep ring buffers of 17408 (hi 32x272=8704, lo +8704)
#define SA   0
#define SA1  52224
#define SW   104448
#define SRED 156672
#define RSM  164864

// hgemm smem (bytes)
#define HA_L 18432
#define HB_H 36864
#define HB_L 46080
#define HBUF 55296
#define HSM  (2*HBUF)

// ---------------- device scratch ----------------
__device__ __align__(16) float g_gx0[(size_t)TT*BB*H2];   // [t][m][n]
__device__ __align__(16) float g_cx0[(size_t)TT*BB*H];
__device__ __align__(16) float g_outT[(size_t)TT*BB*H];
__device__ __align__(16) float g_h0m[2][BB*H];
__device__ __align__(16) float g_h1m[BB*H];
__device__ __align__(16) float g_u0m[BB*H];
__device__ __align__(16) float g_u1m[BB*H];
// bf16 state planes (A operands), m-major [m][k]
__device__ __align__(16) bf16 g_h0h[2][BB*H], g_h0l[2][BB*H];
__device__ __align__(16) bf16 g_h1h[BB*H],  g_h1l[BB*H];
__device__ __align__(16) bf16 g_rh0h[BB*H], g_rh0l[BB*H];
__device__ __align__(16) bf16 g_rh1h[BB*H], g_rh1l[BB*H];
// bf16 recurrent weight planes, [n][k]
__device__ __align__(16) bf16 g_wgt0h[(size_t)H2*H],  g_wgt0l[(size_t)H2*H];
__device__ __align__(16) bf16 g_wgt1h[(size_t)H2*H2], g_wgt1l[(size_t)H2*H2];
__device__ __align__(16) bf16 g_wct0h[(size_t)H*H],   g_wct0l[(size_t)H*H];
__device__ __align__(16) bf16 g_wct1h[(size_t)H*H2],  g_wct1l[(size_t)H*H2];
// hgemm planes
__device__ __align__(16) bf16 g_xh[(size_t)MROWS*H], g_xl[(size_t)MROWS*H];
__device__ __align__(16) bf16 g_oh[(size_t)MROWS*H], g_ol[(size_t)MROWS*H];
__device__ __align__(16) bf16 g_wgh[(size_t)H2*H],  g_wgl[(size_t)H2*H];
__device__ __align__(16) bf16 g_wch[(size_t)H*H],   g_wcl[(size_t)H*H];
__device__ __align__(16) bf16 g_eh[(size_t)VPAD*H], g_el[(size_t)VPAD*H];
__device__ volatile unsigned g_cnt;
__device__ volatile unsigned g_gen;

// ---------------- helpers ----------------
__device__ __forceinline__ float sigf(float x){ return __fdividef(1.f, 1.f+__expf(-x)); }
__device__ __forceinline__ float tanhx(float x){ return 1.f-__fdividef(2.f, __expf(2.f*x)+1.f); }

__device__ __forceinline__ void cp16(void* d, const void* s){
    unsigned ds = (unsigned)__cvta_generic_to_shared(d);
    asm volatile("cp.async.cg.shared.global [%0], [%1], 16;" :: "r"(ds), "l"(s) : "memory");
}
#define CP_COMMIT asm volatile("cp.async.commit_group;" ::: "memory")
#define CP_WAIT0  asm volatile("cp.async.wait_group 0;" ::: "memory")
#define CP_WAIT1  asm volatile("cp.async.wait_group 1;" ::: "memory")

__device__ __forceinline__ void gsync(){
    __threadfence();
    __syncthreads();
    if (threadIdx.x == 0){
        unsigned gen = g_gen;
        unsigned old = atomicAdd((unsigned*)&g_cnt, 1u);
        if (old == NB-1){ g_cnt = 0; __threadfence(); g_gen = gen+1; }
        else { while (g_gen == gen) { __nanosleep(40); } }
    }
    __syncthreads();
}

__device__ __forceinline__ void ldm4(unsigned& r0, unsigned& r1, unsigned& r2, unsigned& r3,
                                     unsigned addr){
    asm volatile("ldmatrix.sync.aligned.m8n8.x4.shared.b16 {%0,%1,%2,%3}, [%4];"
        : "=r"(r0), "=r"(r1), "=r"(r2), "=r"(r3) : "r"(addr));
}
__device__ __forceinline__ void mma16816(float* c, const unsigned* a, const unsigned* b){
    asm volatile("mma.sync.aligned.m16n8k16.row.col.f32.bf16.bf16.f32 "
        "{%0,%1,%2,%3},{%4,%5,%6,%7},{%8,%9},{%0,%1,%2,%3};"
        : "+f"(c[0]), "+f"(c[1]), "+f"(c[2]), "+f"(c[3])
        : "r"(a[0]), "r"(a[1]), "r"(a[2]), "r"(a[3]), "r"(b[0]), "r"(b[1]));
}
__device__ __forceinline__ void wsplit(float v, bf16* hp, bf16* lp, size_t o){
    bf16 h = __float2bfloat16(v);
    hp[o] = h; lp[o] = __float2bfloat16(v - __bfloat162float(h));
}

// ---------------- prep kernels ----------------
__global__ void prep_wq(const float* __restrict__ Wg0, const float* __restrict__ Wg1,
                        const float* __restrict__ Wc0, const float* __restrict__ Wc1){
    __shared__ float s[32][33];
    int b = blockIdx.x;
    const float* src; bf16 *dh, *dl; int srow0, ld, ldd, bx, by;
    if (b < 2048){      src=Wg0; srow0=1024; ld=H2; dh=g_wgt0h; dl=g_wgt0l; ldd=H;  bx=b&31; by=b>>5; }
    else if (b<6144){ int q=b-2048; src=Wg1; srow0=0; ld=H2; dh=g_wgt1h; dl=g_wgt1l; ldd=H2; bx=q&63; by=q>>6; }
    else if (b<7168){ int q=b-6144; src=Wc0; srow0=1024; ld=H; dh=g_wct0h; dl=g_wct0l; ldd=H; bx=q&31; by=q>>5; }
    else {            int q=b-7168; src=Wc1; srow0=0; ld=H; dh=g_wct1h; dl=g_wct1l; ldd=H2; bx=q&63; by=q>>6; }
    int kb = bx*32, nb = by*32;
    int t = threadIdx.x, tx = t&31, ty = t>>5;
#pragma unroll
    for (int i=0;i<32;i+=8) s[ty+i][tx] = src[(size_t)(srow0+kb+ty+i)*ld + nb+tx];
    __syncthreads();
#pragma unroll
    for (int i=0;i<32;i+=8)
        wsplit(s[tx][ty+i], dh, dl, (size_t)(nb+ty+i)*ldd + kb+tx);
}

__global__ void prep_cv(const int* __restrict__ idx, const float* __restrict__ emb,
                        const float* __restrict__ Wg0, const float* __restrict__ Wc0){
    __shared__ float s[32][33];
    int b = blockIdx.x, t = threadIdx.x;
    if (b < 4096){
        float4 v = ((const float4*)(emb + (size_t)idx[b]*H))[t];
        float a[4] = {v.x,v.y,v.z,v.w};
        size_t o = (size_t)b*H + t*4;
#pragma unroll
        for (int j=0;j<4;j++) wsplit(a[j], g_xh, g_xl, o+j);
    } else if (b < 7168){
        const float* src; bf16 *hi, *lo; int ld, kb, nb;
        if (b < 6144){ int q=b-4096; src=Wg0; ld=H2; hi=g_wgh; lo=g_wgl; kb=(q&31)*32; nb=(q>>5)*32; }
        else         { int q=b-6144; src=Wc0; ld=H;  hi=g_wch; lo=g_wcl; kb=(q&31)*32; nb=(q>>5)*32; }
        int tx = t&31, ty = t>>5;
#pragma unroll
        for (int i=0;i<32;i+=8) s[ty+i][tx] = src[(size_t)(kb+ty+i)*ld + nb+tx];
        __syncthreads();
#pragma unroll
        for (int i=0;i<32;i+=8)
            wsplit(s[tx][ty+i], hi, lo, (size_t)(nb+ty+i)*H + kb+tx);
    } else {
        int row = b - 7168;
        size_t o = (size_t)row*H + t*4;
        if (row < VOCAB){
            float4 v = ((const float4*)(emb + (size_t)row*H))[t];
            float a[4] = {v.x,v.y,v.z,v.w};
#pragma unroll
            for (int j=0;j<4;j++) wsplit(a[j], g_eh, g_el, o+j);
        } else {
#pragma unroll
            for (int j=0;j<4;j++){ g_eh[o+j]=__float2bfloat16(0.f); g_el[o+j]=__float2bfloat16(0.f); }
        }
    }
}

__global__ void outconv(const float* __restrict__ outT){
    int r = blockIdx.x, tid = threadIdx.x;
    int m = r>>7, t = r&127;
    float4 v = ((const float4*)(outT + ((size_t)t*BB + m)*H))[tid];
    float a[4] = {v.x,v.y,v.z,v.w};
    size_t o = (size_t)r*H + tid*4;
#pragma unroll
    for (int j=0;j<4;j++) wsplit(a[j], g_oh, g_ol, o+j);
}

// ---------------- HMMA bf16-split big GEMM (r9, proven) ----------------
template<bool GRUL>
__global__ void __launch_bounds__(256, 1)
hgemm(const bf16* __restrict__ Ah, const bf16* __restrict__ Al,
      const bf16* __restrict__ Bh, const bf16* __restrict__ Bl,
      const float* __restrict__ bias, float* __restrict__ C, int N)
{
    extern __shared__ __align__(16) char smc[];
    const int tid = threadIdx.x, wid = tid>>5, lane = tid&31;
    const int n0 = blockIdx.x*64, m0 = blockIdx.y*128;
    const int wm = wid&3, wn = wid>>2;
    unsigned sb = (unsigned)__cvta_generic_to_shared(smc);

    auto stage = [&](int kc){
        char* base = smc + (kc&1)*HBUF;
#pragma unroll
        for (int u=0;u<8;u++){
            int e = tid + u*256;
            int pl = e>>10, i = e&1023, row = i>>3, g = i&7;
            const bf16* src = (pl?Al:Ah) + (size_t)(m0+row)*H + kc*64 + g*8;
            cp16(base + (pl?HA_L:0) + row*144 + g*16, src);
        }
#pragma unroll
        for (int u=0;u<4;u++){
            int e = tid + u*256;
            int pl = e>>9, i = e&511, row = i>>3, g = i&7;
            const bf16* src = (pl?Bl:Bh) + (size_t)(n0+row)*H + kc*64 + g*8;
            cp16(base + (pl?HB_L:HB_H) + row*144 + g*16, src);
        }
    };

    float cc[2][4][4];
#pragma unroll
    for (int a=0;a<2;a++)
#pragma unroll
        for (int b=0;b<4;b++)
#pragma unroll
            for (int q=0;q<4;q++) cc[a][b][q] = 0.f;

    stage(0); CP_COMMIT;
    for (int kc=0;kc<16;kc++){
        if (kc < 15){ stage(kc+1); CP_COMMIT; CP_WAIT1; } else CP_WAIT0;
        __syncthreads();
        unsigned bufb = sb + (kc&1)*HBUF;
        unsigned aB = bufb + (wm*32 + (lane&15))*144 + ((lane>>4)&1)*16;
        unsigned bB = bufb + HB_H + (wn*32 + (lane&7) + ((lane>>4)&1)*8)*144 + ((lane>>3)&1)*16;
#pragma unroll
        for (int ks=0;ks<4;ks++){
            unsigned ah[8], al[8], bh[8], bl[8];
            ldm4(ah[0],ah[1],ah[2],ah[3], aB + ks*32);
            ldm4(ah[4],ah[5],ah[6],ah[7], aB + 16*144 + ks*32);
            ldm4(al[0],al[1],al[2],al[3], aB + HA_L + ks*32);
            ldm4(al[4],al[5],al[6],al[7], aB + HA_L + 16*144 + ks*32);
            ldm4(bh[0],bh[1],bh[2],bh[3], bB + ks*32);
            ldm4(bh[4],bh[5],bh[6],bh[7], bB + 16*144 + ks*32);
            ldm4(bl[0],bl[1],bl[2],bl[3], bB + (HB_L-HB_H) + ks*32);
            ldm4(bl[4],bl[5],bl[6],bl[7], bB + (HB_L-HB_H) + 16*144 + ks*32);
#pragma unroll
            for (int fm=0;fm<2;fm++)
#pragma unroll
                for (int fn=0;fn<4;fn++){
                    mma16816(cc[fm][fn], ah+fm*4, bh+fn*2);
                    mma16816(cc[fm][fn], ah+fm*4, bl+fn*2);
                    mma16816(cc[fm][fn], al+fm*4, bh+fn*2);
                }
        }
        __syncthreads();
    }

    const int rb = lane>>2, cb = (lane&3)*2;
#pragma unroll
    for (int fm=0;fm<2;fm++){
#pragma unroll
        for (int half=0;half<2;half++){
            int r = m0 + wm*32 + fm*16 + rb + half*8;
            int r2 = GRUL ? ((r & 127)*BB + (r >> 7)) : r;
            float* crow = C + (size_t)r2*N;
#pragma unroll
            for (int fn=0;fn<4;fn++){
                int n = n0 + wn*32 + fn*8 + cb;
                if (n < N){
                    float2 v;
                    v.x = cc[fm][fn][half*2+0];
                    v.y = cc[fm][fn][half*2+1];
                    if (bias){
                        float2 b = *(const float2*)(bias + n);
                        v.x += b.x; v.y += b.y;
                    }
                    *(float2*)(crow + n) = v;
                }
            }
        }
    }
}

// ---------------- persistent HMMA recurrence (3-deep cp.async ring) ----------------
__global__ void __launch_bounds__(NTHR, 1)
rnn_persist(const float* __restrict__ bg0, const float* __restrict__ bc0,
            const float* __restrict__ bg1, const float* __restrict__ bc1)
{
    extern __shared__ __align__(16) char smc[];
    const int tid = threadIdx.x, c = blockIdx.x;
    const int lane = tid & 31, w = tid >> 5;
    unsigned sb = (unsigned)__cvta_generic_to_shared(smc);
    float* redf = (float*)(smc + SRED);

    {   int gt = c*NTHR + tid;
        bf16 z = __float2bfloat16(0.f);
        g_h0m[0][gt]=0.f; g_h1m[gt]=0.f;
        g_h0h[0][gt]=z; g_h0l[0][gt]=z; g_h1h[gt]=z; g_h1l[gt]=z;
    }
    gsync();

    const int ngA = w & 3, ksA = w >> 2;   // 4 n-groups x 2 k-split
    const int lB = w & 1, ksB = w >> 1;    // 2 layers x 4 k-split

    int cur = 0;
    for (int t = 0; t <= TT; t++){
        const bool do0 = (t < TT), do1 = (t > 0);
        const int nc = do1 ? 16 : 8;

        // ===================== PHASE A: gates =====================
        {
            auto stage = [&](int kc){
                int bi = kc % 3;
                char* Ab = smc + SA + bi*17408;
                const bf16 *sh, *sl; int ko;
                if (kc < 8){ sh = g_h0h[cur]; sl = g_h0l[cur]; ko = kc*128; }
                else       { sh = g_h1h;      sl = g_h1l;      ko = (kc-8)*128; }
                #pragma unroll
                for (int u=0;u<2;u++){
                    int e = tid + u*NTHR; int row = e>>4, g = e&15;
                    cp16(Ab + row*272 + g*16,        sh + (size_t)row*H + ko + g*8);
                    cp16(Ab + 8704 + row*272 + g*16, sl + (size_t)row*H + ko + g*8);
                }
                char* Wb = smc + SW + bi*17408;
                {   int r = tid>>4, g = tid&15;
                    size_t o1 = (size_t)(c*16 + r)*H2 + kc*128 + g*8;
                    cp16(Wb + (16+r)*272 + g*16,        g_wgt1h + o1);
                    cp16(Wb + 8704 + (16+r)*272 + g*16, g_wgt1l + o1);
                    if (kc < 8){
                        size_t o0 = (size_t)(c*16 + r)*H + kc*128 + g*8;
                        cp16(Wb + r*272 + g*16,        g_wgt0h + o0);
                        cp16(Wb + 8704 + r*272 + g*16, g_wgt0l + o0);
                    }
                }
                CP_COMMIT;
            };
            stage(0); stage(1);
            float c0[2][4], c1[2][4], c2[2][4];
            #pragma unroll
            for (int fm=0;fm<2;fm++)
                #pragma unroll
                for (int q=0;q<4;q++){ c0[fm][q]=0.f; c1[fm][q]=0.f; c2[fm][q]=0.f; }

            for (int kc=0;kc<nc;kc++){
                CP_WAIT1;
                __syncthreads();
                if (kc+2 < nc) stage(kc+2);
                const bool act = (ngA < 2) ? (do0 && kc < 8) : do1;
                if (act){
                    int bi = kc % 3;
                    unsigned sA = sb + SA + bi*17408;
                    unsigned sW = sb + SW + bi*17408;
                    unsigned wB = sW + (ngA*8 + (lane&7))*272 + ((lane>>3)&3)*16 + ksA*128;
                    unsigned bh[8], bl[8];
                    ldm4(bh[0],bh[1],bh[2],bh[3], wB);
                    ldm4(bh[4],bh[5],bh[6],bh[7], wB + 64);
                    ldm4(bl[0],bl[1],bl[2],bl[3], wB + 8704);
                    ldm4(bl[4],bl[5],bl[6],bl[7], wB + 8704 + 64);
                    unsigned aB = sA + (lane&15)*272 + ((lane>>4)&1)*16 + ksA*128;
                    #pragma unroll
                    for (int s=0;s<4;s++){
                        unsigned a0[4], a1[4], l0[4], l1[4];
                        ldm4(a0[0],a0[1],a0[2],a0[3], aB + s*32);
                        ldm4(a1[0],a1[1],a1[2],a1[3], aB + 16*272 + s*32);
                        ldm4(l0[0],l0[1],l0[2],l0[3], aB + 8704 + s*32);
                        ldm4(l1[0],l1[1],l1[2],l1[3], aB + 8704 + 16*272 + s*32);
                        mma16816(c0[0], a0, bh+2*s); mma16816(c0[1], a1, bh+2*s);
                        mma16816(c1[0], a0, bl+2*s); mma16816(c1[1], a1, bl+2*s);
                        mma16816(c2[0], l0, bh+2*s); mma16816(c2[1], l1, bh+2*s);
                    }
                }
            }
            __syncthreads();
            #pragma unroll
            for (int fm=0;fm<2;fm++)
                #pragma unroll
                for (int q=0;q<4;q++){
                    int m = fm*16 + (lane>>2) + (q>>1)*8;
                    int nl = (lane&3)*2 + (q&1);
                    redf[((ksA*4+ngA)*32 + m)*8 + nl] = c0[fm][q]+c1[fm][q]+c2[fm][q];
                }
            __syncthreads();
            #pragma unroll
            for (int u=0;u<4;u++){
                int o = tid + u*NTHR;
                int m = o>>5, col = o&31;
                int ng2 = col>>3, nl = col&7;
                float s = redf[(ng2*32+m)*8+nl] + redf[((4+ng2)*32+m)*8+nl];
                if (col < 16){
                    if (do0){
                        int n = c*16 + col;
                        s += g_gx0[((size_t)t*BB+m)*H2 + n] + bg0[n];
                        float g = sigf(s);
                        if (n < H){
                            float v = g * g_h0m[cur][m*H+n];
                            wsplit(v, g_rh0h, g_rh0l, (size_t)m*H + n);
                        } else g_u0m[m*H + n-H] = g;
                    }
                } else {
                    if (do1){
                        int n = c*16 + col - 16;
                        s += bg1[n];
                        float g = sigf(s);
                        if (n < H){
                            float v = g * g_h1m[m*H+n];
                            wsplit(v, g_rh1h, g_rh1l, (size_t)m*H + n);
                        } else g_u1m[m*H + n-H] = g;
                    }
                }
            }
        }
        gsync();

        // ===================== PHASE B: candidates + update =====================
        {
            auto stage = [&](int kc){
                int bi = kc % 3;
                char* A1b = smc + SA1 + bi*17408;
                const bf16 *sh, *sl; int ko;
                if (kc < 8){ sh = g_h0h[cur]; sl = g_h0l[cur]; ko = kc*128; }
                else       { sh = g_rh1h;     sl = g_rh1l;     ko = (kc-8)*128; }
                #pragma unroll
                for (int u=0;u<2;u++){
                    int e = tid + u*NTHR; int row = e>>4, g = e&15;
                    cp16(A1b + row*272 + g*16,        sh + (size_t)row*H + ko + g*8);
                    cp16(A1b + 8704 + row*272 + g*16, sl + (size_t)row*H + ko + g*8);
                }
                if (kc < 8){
                    char* A0b = smc + SA + bi*17408;
                    #pragma unroll
                    for (int u=0;u<2;u++){
                        int e = tid + u*NTHR; int row = e>>4, g = e&15;
                        cp16(A0b + row*272 + g*16,        g_rh0h + (size_t)row*H + kc*128 + g*8);
                        cp16(A0b + 8704 + row*272 + g*16, g_rh0l + (size_t)row*H + kc*128 + g*8);
                    }
                }
                char* Wb = smc + SW + bi*17408;
                {   int pl = tid>>7, i = tid&127, r = i>>4, g = i&15;
                    size_t o1 = (size_t)(c*8 + r)*H2 + kc*128 + g*8;
                    cp16(Wb + pl*8704 + (8+r)*272 + g*16, (pl? g_wct1l : g_wct1h) + o1);
                    if (kc < 8){
                        size_t o0 = (size_t)(c*8 + r)*H + kc*128 + g*8;
                        cp16(Wb + pl*8704 + r*272 + g*16, (pl? g_wct0l : g_wct0h) + o0);
                    }
                }
                CP_COMMIT;
            };
            stage(0); stage(1);
            float c0[2][4], c1[2][4], c2[2][4];
            #pragma unroll
            for (int fm=0;fm<2;fm++)
                #pragma unroll
                for (int q=0;q<4;q++){ c0[fm][q]=0.f; c1[fm][q]=0.f; c2[fm][q]=0.f; }

            for (int kc=0;kc<nc;kc++){
                CP_WAIT1;
                __syncthreads();
                if (kc+2 < nc) stage(kc+2);
                const bool act = (lB == 0) ? (do0 && kc < 8) : do1;
                if (act){
                    int bi = kc % 3;
                    unsigned sAx = sb + (lB ? SA1 : SA) + bi*17408;
                    unsigned sW = sb + SW + bi*17408;
                    unsigned wB = sW + (lB*8 + (lane&7))*272 + ((lane>>3)&3)*16 + ksB*64;
                    unsigned bh[4], bl[4];
                    ldm4(bh[0],bh[1],bh[2],bh[3], wB);
                    ldm4(bl[0],bl[1],bl[2],bl[3], wB + 8704);
                    unsigned aB = sAx + (lane&15)*272 + ((lane>>4)&1)*16 + ksB*64;
                    #pragma unroll
                    for (int s=0;s<2;s++){
                        unsigned a0[4], a1[4], l0[4], l1[4];
                        ldm4(a0[0],a0[1],a0[2],a0[3], aB + s*32);
                        ldm4(a1[0],a1[1],a1[2],a1[3], aB + 16*272 + s*32);
                        ldm4(l0[0],l0[1],l0[2],l0[3], aB + 8704 + s*32);
                        ldm4(l1[0],l1[1],l1[2],l1[3], aB + 8704 + 16*272 + s*32);
                        mma16816(c0[0], a0, bh+2*s); mma16816(c0[1], a1, bh+2*s);
                        mma16816(c1[0], a0, bl+2*s); mma16816(c1[1], a1, bl+2*s);
                        mma16816(c2[0], l0, bh+2*s); mma16816(c2[1], l1, bh+2*s);
                    }
                }
            }
            __syncthreads();
            #pragma unroll
            for (int fm=0;fm<2;fm++)
                #pragma unroll
                for (int q=0;q<4;q++){
                    int m = fm*16 + (lane>>2) + (q>>1)*8;
                    int nl = (lane&3)*2 + (q&1);
                    redf[((ksB*2+lB)*32 + m)*8 + nl] = c0[fm][q]+c1[fm][q]+c2[fm][q];
                }
            __syncthreads();
            #pragma unroll
            for (int u=0;u<2;u++){
                int o = tid + u*NTHR;
                int m = o>>4, col = o&15;
                int lg = col>>3, nl = col&7;
                float s = redf[((0*2+lg)*32+m)*8+nl] + redf[((1*2+lg)*32+m)*8+nl]
                        + redf[((2*2+lg)*32+m)*8+nl] + redf[((3*2+lg)*32+m)*8+nl];
                if (lg == 0){
                    if (do0){
                        int n = c*8 + nl;
                        s += g_cx0[((size_t)t*BB+m)*H + n] + bc0[n];
                        float cc = tanhx(s);
                        float uu = g_u0m[m*H+n];
                        float hn = uu * g_h0m[cur][m*H+n] + (1.f-uu)*cc;
                        g_h0m[cur^1][m*H+n] = hn;
                        wsplit(hn, g_h0h[cur^1], g_h0l[cur^1], (size_t)m*H + n);
                    }
                } else {
                    if (do1){
                        int n = c*8 + nl;
                        s += bc1[n];
                        float cc = tanhx(s);
                        float uu = g_u1m[m*H+n];
                        float hn = uu * g_h1m[m*H+n] + (1.f-uu)*cc;
                        g_h1m[m*H+n] = hn;
                        wsplit(hn, g_h1h, g_h1l, (size_t)m*H + n);
                        g_outT[((size_t)(t-1)*BB+m)*H + n] = hn;
                    }
                }
            }
        }
        cur ^= 1;
        gsync();
    }
}

// ---------------- launch ----------------
extern "C" void kernel_launch(void* const* d_in, const int* in_sizes, int n_in,
                              void* d_out, int out_size)
{
    const int*   idx = (const int*)  d_in[0];
    const float* emb = (const float*)d_in[1];
    const float* Wg0 = (const float*)d_in[2];
    const float* bg0 = (const float*)d_in[3];
    const float* Wc0 = (const float*)d_in[4];
    const float* bc0 = (const float*)d_in[5];
    const float* Wg1 = (const float*)d_in[6];
    const float* bg1 = (const float*)d_in[7];
    const float* Wc1 = (const float*)d_in[8];
    const float* bc1 = (const float*)d_in[9];
    const float* smb = (const float*)d_in[10];
    float* out = (float*)d_out;

    float *pgx0,*pcx0,*poutT;
    bf16 *pxh,*pxl,*poh,*pol,*pwgh,*pwgl,*pwch,*pwcl,*peh,*pel;
    cudaGetSymbolAddress((void**)&pgx0,  g_gx0);
    cudaGetSymbolAddress((void**)&pcx0,  g_cx0);
    cudaGetSymbolAddress((void**)&poutT, g_outT);
    cudaGetSymbolAddress((void**)&pxh,   g_xh);
    cudaGetSymbolAddress((void**)&pxl,   g_xl);
    cudaGetSymbolAddress((void**)&poh,   g_oh);
    cudaGetSymbolAddress((void**)&pol,   g_ol);
    cudaGetSymbolAddress((void**)&pwgh,  g_wgh);
    cudaGetSymbolAddress((void**)&pwgl,  g_wgl);
    cudaGetSymbolAddress((void**)&pwch,  g_wch);
    cudaGetSymbolAddress((void**)&pwcl,  g_wcl);
    cudaGetSymbolAddress((void**)&peh,   g_eh);
    cudaGetSymbolAddress((void**)&pel,   g_el);

    static bool attr_set = false;
    if (!attr_set){
        cudaFuncSetAttribute(rnn_persist, cudaFuncAttributeMaxDynamicSharedMemorySize, RSM);
        cudaFuncSetAttribute(hgemm<true>,  cudaFuncAttributeMaxDynamicSharedMemorySize, HSM);
        cudaFuncSetAttribute(hgemm<false>, cudaFuncAttributeMaxDynamicSharedMemorySize, HSM);
        attr_set = true;
    }

    prep_wq<<<9216, 256>>>(Wg0, Wg1, Wc0, Wc1);
    prep_cv<<<7168 + VPAD, 256>>>(idx, emb, Wg0, Wc0);

    hgemm<true><<<dim3(H2/64, MROWS/128), 256, HSM>>>(pxh, pxl, pwgh, pwgl, nullptr, pgx0, H2);
    hgemm<true><<<dim3(H/64,  MROWS/128), 256, HSM>>>(pxh, pxl, pwch, pwcl, nullptr, pcx0, H);

    rnn_persist<<<NB, NTHR, RSM>>>(bg0, bc0, bg1, bc1);

    outconv<<<MROWS, 256>>>(poutT);
    hgemm<false><<<dim3(VPAD/64, MROWS/128), 256, HSM>>>(poh, pol, peh, pel, smb, out, VOCAB);
}

// round 13
// speedup vs baseline: 1.4046x; 1.0327x over previous
#include <cuda_runtime.h>
#include <cuda_bf16.h>
#include <math.h>
typedef unsigned long long ull;
typedef __nv_bfloat16 bf16;

#define VOCAB 10000
#define VPAD  10048
#define H 1024
#define H2 2048
#define BB 32
#define TT 128
#define MROWS (BB*TT)
#define NB 128
#define NTHR 256

// rnn smem layout (bytes): 4-deep ring buffers of 17408 (hi 32x272=8704, lo +8704)
#define SA   0
#define SA1  69632
#define SW   139264
#define SRED 208896
#define RSM  217088

// hgemm smem (bytes)
#define HA_L 18432
#define HB_H 36864
#define HB_L 46080
#define HBUF 55296
#define HSM  (2*HBUF)

// ---------------- device scratch ----------------
__device__ __align__(16) float g_gx0[(size_t)TT*BB*H2];   // [t][m][n]
__device__ __align__(16) float g_cx0[(size_t)TT*BB*H];
__device__ __align__(16) float g_outT[(size_t)TT*BB*H];
__device__ __align__(16) float g_h0m[2][BB*H];
__device__ __align__(16) float g_h1m[BB*H];
__device__ __align__(16) float g_u0m[BB*H];
__device__ __align__(16) float g_u1m[BB*H];
// bf16 state planes (A operands), m-major [m][k]
__device__ __align__(16) bf16 g_h0h[2][BB*H], g_h0l[2][BB*H];
__device__ __align__(16) bf16 g_h1h[BB*H],  g_h1l[BB*H];
__device__ __align__(16) bf16 g_rh0h[BB*H], g_rh0l[BB*H];
__device__ __align__(16) bf16 g_rh1h[BB*H], g_rh1l[BB*H];
// bf16 recurrent weight planes, [n][k]
__device__ __align__(16) bf16 g_wgt0h[(size_t)H2*H],  g_wgt0l[(size_t)H2*H];
__device__ __align__(16) bf16 g_wgt1h[(size_t)H2*H2], g_wgt1l[(size_t)H2*H2];
__device__ __align__(16) bf16 g_wct0h[(size_t)H*H],   g_wct0l[(size_t)H*H];
__device__ __align__(16) bf16 g_wct1h[(size_t)H*H2],  g_wct1l[(size_t)H*H2];
// hgemm planes
__device__ __align__(16) bf16 g_xh[(size_t)MROWS*H], g_xl[(size_t)MROWS*H];
__device__ __align__(16) bf16 g_oh[(size_t)MROWS*H], g_ol[(size_t)MROWS*H];
__device__ __align__(16) bf16 g_wgh[(size_t)H2*H],  g_wgl[(size_t)H2*H];
__device__ __align__(16) bf16 g_wch[(size_t)H*H],   g_wcl[(size_t)H*H];
__device__ __align__(16) bf16 g_eh[(size_t)VPAD*H], g_el[(size_t)VPAD*H];
__device__ volatile unsigned g_cnt;
__device__ volatile unsigned g_gen;

// ---------------- helpers ----------------
__device__ __forceinline__ float sigf(float x){ return __fdividef(1.f, 1.f+__expf(-x)); }
__device__ __forceinline__ float tanhx(float x){ return 1.f-__fdividef(2.f, __expf(2.f*x)+1.f); }

__device__ __forceinline__ void cp16(void* d, const void* s){
    unsigned ds = (unsigned)__cvta_generic_to_shared(d);
    asm volatile("cp.async.cg.shared.global [%0], [%1], 16;" :: "r"(ds), "l"(s) : "memory");
}
#define CP_COMMIT asm volatile("cp.async.commit_group;" ::: "memory")
#define CP_WAIT0  asm volatile("cp.async.wait_group 0;" ::: "memory")
#define CP_WAIT1  asm volatile("cp.async.wait_group 1;" ::: "memory")
#define CP_WAIT2  asm volatile("cp.async.wait_group 2;" ::: "memory")

// honest wait: chunk kc must be COMPLETE before MAC; rem = chunks still staged after kc
__device__ __forceinline__ void cp_wait_rem(int rem){
    if (rem >= 2)      CP_WAIT2;
    else if (rem == 1) CP_WAIT1;
    else               CP_WAIT0;
}

__device__ __forceinline__ void gsync(){
    __threadfence();
    __syncthreads();
    if (threadIdx.x == 0){
        unsigned gen = g_gen;
        unsigned old = atomicAdd((unsigned*)&g_cnt, 1u);
        if (old == NB-1){ g_cnt = 0; __threadfence(); g_gen = gen+1; }
        else { while (g_gen == gen) { __nanosleep(40); } }
    }
    __syncthreads();
}

__device__ __forceinline__ void ldm4(unsigned& r0, unsigned& r1, unsigned& r2, unsigned& r3,
                                     unsigned addr){
    asm volatile("ldmatrix.sync.aligned.m8n8.x4.shared.b16 {%0,%1,%2,%3}, [%4];"
        : "=r"(r0), "=r"(r1), "=r"(r2), "=r"(r3) : "r"(addr));
}
__device__ __forceinline__ void mma16816(float* c, const unsigned* a, const unsigned* b){
    asm volatile("mma.sync.aligned.m16n8k16.row.col.f32.bf16.bf16.f32 "
        "{%0,%1,%2,%3},{%4,%5,%6,%7},{%8,%9},{%0,%1,%2,%3};"
        : "+f"(c[0]), "+f"(c[1]), "+f"(c[2]), "+f"(c[3])
        : "r"(a[0]), "r"(a[1]), "r"(a[2]), "r"(a[3]), "r"(b[0]), "r"(b[1]));
}
__device__ __forceinline__ void wsplit(float v, bf16* hp, bf16* lp, size_t o){
    bf16 h = __float2bfloat16(v);
    hp[o] = h; lp[o] = __float2bfloat16(v - __bfloat162float(h));
}

// ---------------- prep kernels ----------------
__global__ void prep_wq(const float* __restrict__ Wg0, const float* __restrict__ Wg1,
                        const float* __restrict__ Wc0, const float* __restrict__ Wc1){
    __shared__ float s[32][33];
    int b = blockIdx.x;
    const float* src; bf16 *dh, *dl; int srow0, ld, ldd, bx, by;
    if (b < 2048){      src=Wg0; srow0=1024; ld=H2; dh=g_wgt0h; dl=g_wgt0l; ldd=H;  bx=b&31; by=b>>5; }
    else if (b<6144){ int q=b-2048; src=Wg1; srow0=0; ld=H2; dh=g_wgt1h; dl=g_wgt1l; ldd=H2; bx=q&63; by=q>>6; }
    else if (b<7168){ int q=b-6144; src=Wc0; srow0=1024; ld=H; dh=g_wct0h; dl=g_wct0l; ldd=H; bx=q&31; by=q>>5; }
    else {            int q=b-7168; src=Wc1; srow0=0; ld=H; dh=g_wct1h; dl=g_wct1l; ldd=H2; bx=q&63; by=q>>6; }
    int kb = bx*32, nb = by*32;
    int t = threadIdx.x, tx = t&31, ty = t>>5;
#pragma unroll
    for (int i=0;i<32;i+=8) s[ty+i][tx] = src[(size_t)(srow0+kb+ty+i)*ld + nb+tx];
    __syncthreads();
#pragma unroll
    for (int i=0;i<32;i+=8)
        wsplit(s[tx][ty+i], dh, dl, (size_t)(nb+ty+i)*ldd + kb+tx);
}

__global__ void prep_cv(const int* __restrict__ idx, const float* __restrict__ emb,
                        const float* __restrict__ Wg0, const float* __restrict__ Wc0){
    __shared__ float s[32][33];
    int b = blockIdx.x, t = threadIdx.x;
    if (b < 4096){
        float4 v = ((const float4*)(emb + (size_t)idx[b]*H))[t];
        float a[4] = {v.x,v.y,v.z,v.w};
        size_t o = (size_t)b*H + t*4;
#pragma unroll
        for (int j=0;j<4;j++) wsplit(a[j], g_xh, g_xl, o+j);
    } else if (b < 7168){
        const float* src; bf16 *hi, *lo; int ld, kb, nb;
        if (b < 6144){ int q=b-4096; src=Wg0; ld=H2; hi=g_wgh; lo=g_wgl; kb=(q&31)*32; nb=(q>>5)*32; }
        else         { int q=b-6144; src=Wc0; ld=H;  hi=g_wch; lo=g_wcl; kb=(q&31)*32; nb=(q>>5)*32; }
        int tx = t&31, ty = t>>5;
#pragma unroll
        for (int i=0;i<32;i+=8) s[ty+i][tx] = src[(size_t)(kb+ty+i)*ld + nb+tx];
        __syncthreads();
#pragma unroll
        for (int i=0;i<32;i+=8)
            wsplit(s[tx][ty+i], hi, lo, (size_t)(nb+ty+i)*H + kb+tx);
    } else {
        int row = b - 7168;
        size_t o = (size_t)row*H + t*4;
        if (row < VOCAB){
            float4 v = ((const float4*)(emb + (size_t)row*H))[t];
            float a[4] = {v.x,v.y,v.z,v.w};
#pragma unroll
            for (int j=0;j<4;j++) wsplit(a[j], g_eh, g_el, o+j);
        } else {
#pragma unroll
            for (int j=0;j<4;j++){ g_eh[o+j]=__float2bfloat16(0.f); g_el[o+j]=__float2bfloat16(0.f); }
        }
    }
}

__global__ void outconv(const float* __restrict__ outT){
    int r = blockIdx.x, tid = threadIdx.x;
    int m = r>>7, t = r&127;
    float4 v = ((const float4*)(outT + ((size_t)t*BB + m)*H))[tid];
    float a[4] = {v.x,v.y,v.z,v.w};
    size_t o = (size_t)r*H + tid*4;
#pragma unroll
    for (int j=0;j<4;j++) wsplit(a[j], g_oh, g_ol, o+j);
}

// ---------------- HMMA bf16-split big GEMM (2 CTAs/SM) ----------------
template<bool GRUL>
__global__ void __launch_bounds__(256, 2)
hgemm(const bf16* __restrict__ Ah, const bf16* __restrict__ Al,
      const bf16* __restrict__ Bh, const bf16* __restrict__ Bl,
      const float* __restrict__ bias, float* __restrict__ C, int N)
{
    extern __shared__ __align__(16) char smc[];
    const int tid = threadIdx.x, wid = tid>>5, lane = tid&31;
    const int n0 = blockIdx.x*64, m0 = blockIdx.y*128;
    const int wm = wid&3, wn = wid>>2;
    unsigned sb = (unsigned)__cvta_generic_to_shared(smc);

    auto stage = [&](int kc){
        char* base = smc + (kc&1)*HBUF;
#pragma unroll
        for (int u=0;u<8;u++){
            int e = tid + u*256;
            int pl = e>>10, i = e&1023, row = i>>3, g = i&7;
            const bf16* src = (pl?Al:Ah) + (size_t)(m0+row)*H + kc*64 + g*8;
            cp16(base + (pl?HA_L:0) + row*144 + g*16, src);
        }
#pragma unroll
        for (int u=0;u<4;u++){
            int e = tid + u*256;
            int pl = e>>9, i = e&511, row = i>>3, g = i&7;
            const bf16* src = (pl?Bl:Bh) + (size_t)(n0+row)*H + kc*64 + g*8;
            cp16(base + (pl?HB_L:HB_H) + row*144 + g*16, src);
        }
    };

    float cc[2][4][4];
#pragma unroll
    for (int a=0;a<2;a++)
#pragma unroll
        for (int b=0;b<4;b++)
#pragma unroll
            for (int q=0;q<4;q++) cc[a][b][q] = 0.f;

    stage(0); CP_COMMIT;
    for (int kc=0;kc<16;kc++){
        if (kc < 15){ stage(kc+1); CP_COMMIT; CP_WAIT1; } else CP_WAIT0;
        __syncthreads();
        unsigned bufb = sb + (kc&1)*HBUF;
        unsigned aB = bufb + (wm*32 + (lane&15))*144 + ((lane>>4)&1)*16;
        unsigned bB = bufb + HB_H + (wn*32 + (lane&7) + ((lane>>4)&1)*8)*144 + ((lane>>3)&1)*16;
#pragma unroll
        for (int ks=0;ks<4;ks++){
            unsigned ah[8], al[8], bh[8], bl[8];
            ldm4(ah[0],ah[1],ah[2],ah[3], aB + ks*32);
            ldm4(ah[4],ah[5],ah[6],ah[7], aB + 16*144 + ks*32);
            ldm4(al[0],al[1],al[2],al[3], aB + HA_L + ks*32);
            ldm4(al[4],al[5],al[6],al[7], aB + HA_L + 16*144 + ks*32);
            ldm4(bh[0],bh[1],bh[2],bh[3], bB + ks*32);
            ldm4(bh[4],bh[5],bh[6],bh[7], bB + 16*144 + ks*32);
            ldm4(bl[0],bl[1],bl[2],bl[3], bB + (HB_L-HB_H) + ks*32);
            ldm4(bl[4],bl[5],bl[6],bl[7], bB + (HB_L-HB_H) + 16*144 + ks*32);
#pragma unroll
            for (int fm=0;fm<2;fm++)
#pragma unroll
                for (int fn=0;fn<4;fn++){
                    mma16816(cc[fm][fn], ah+fm*4, bh+fn*2);
                    mma16816(cc[fm][fn], ah+fm*4, bl+fn*2);
                    mma16816(cc[fm][fn], al+fm*4, bh+fn*2);
                }
        }
        __syncthreads();
    }

    const int rb = lane>>2, cb = (lane&3)*2;
#pragma unroll
    for (int fm=0;fm<2;fm++){
#pragma unroll
        for (int half=0;half<2;half++){
            int r = m0 + wm*32 + fm*16 + rb + half*8;
            int r2 = GRUL ? ((r & 127)*BB + (r >> 7)) : r;
            float* crow = C + (size_t)r2*N;
#pragma unroll
            for (int fn=0;fn<4;fn++){
                int n = n0 + wn*32 + fn*8 + cb;
                if (n < N){
                    float2 v;
                    v.x = cc[fm][fn][half*2+0];
                    v.y = cc[fm][fn][half*2+1];
                    if (bias){
                        float2 b = *(const float2*)(bias + n);
                        v.x += b.x; v.y += b.y;
                    }
                    *(float2*)(crow + n) = v;
                }
            }
        }
    }
}

// ---------------- persistent HMMA recurrence (4-deep ring, honest waits) ----------------
__global__ void __launch_bounds__(NTHR, 1)
rnn_persist(const float* __restrict__ bg0, const float* __restrict__ bc0,
            const float* __restrict__ bg1, const float* __restrict__ bc1)
{
    extern __shared__ __align__(16) char smc[];
    const int tid = threadIdx.x, c = blockIdx.x;
    const int lane = tid & 31, w = tid >> 5;
    unsigned sb = (unsigned)__cvta_generic_to_shared(smc);
    float* redf = (float*)(smc + SRED);

    {   int gt = c*NTHR + tid;
        bf16 z = __float2bfloat16(0.f);
        g_h0m[0][gt]=0.f; g_h1m[gt]=0.f;
        g_h0h[0][gt]=z; g_h0l[0][gt]=z; g_h1h[gt]=z; g_h1l[gt]=z;
    }
    gsync();

    const int ngA = w & 3, ksA = w >> 2;   // 4 n-groups x 2 k-split
    const int lB = w & 1, ksB = w >> 1;    // 2 layers x 4 k-split

    int cur = 0;
    for (int t = 0; t <= TT; t++){
        const bool do0 = (t < TT), do1 = (t > 0);
        const int nc = do1 ? 16 : 8;

        // ===================== PHASE A: gates =====================
        {
            auto stage = [&](int kc){
                int bi = kc & 3;
                char* Ab = smc + SA + bi*17408;
                const bf16 *sh, *sl; int ko;
                if (kc < 8){ sh = g_h0h[cur]; sl = g_h0l[cur]; ko = kc*128; }
                else       { sh = g_h1h;      sl = g_h1l;      ko = (kc-8)*128; }
                #pragma unroll
                for (int u=0;u<2;u++){
                    int e = tid + u*NTHR; int row = e>>4, g = e&15;
                    cp16(Ab + row*272 + g*16,        sh + (size_t)row*H + ko + g*8);
                    cp16(Ab + 8704 + row*272 + g*16, sl + (size_t)row*H + ko + g*8);
                }
                char* Wb = smc + SW + bi*17408;
                {   int r = tid>>4, g = tid&15;
                    size_t o1 = (size_t)(c*16 + r)*H2 + kc*128 + g*8;
                    cp16(Wb + (16+r)*272 + g*16,        g_wgt1h + o1);
                    cp16(Wb + 8704 + (16+r)*272 + g*16, g_wgt1l + o1);
                    if (kc < 8){
                        size_t o0 = (size_t)(c*16 + r)*H + kc*128 + g*8;
                        cp16(Wb + r*272 + g*16,        g_wgt0h + o0);
                        cp16(Wb + 8704 + r*272 + g*16, g_wgt0l + o0);
                    }
                }
                CP_COMMIT;
            };
            stage(0); stage(1); stage(2);
            float c0[2][4], c1[2][4], c2[2][4];
            #pragma unroll
            for (int fm=0;fm<2;fm++)
                #pragma unroll
                for (int q=0;q<4;q++){ c0[fm][q]=0.f; c1[fm][q]=0.f; c2[fm][q]=0.f; }

            for (int kc=0;kc<nc;kc++){
                cp_wait_rem(nc-1-kc);
                __syncthreads();
                if (kc+3 < nc) stage(kc+3);
                const bool act = (ngA < 2) ? (do0 && kc < 8) : do1;
                if (act){
                    int bi = kc & 3;
                    unsigned sA = sb + SA + bi*17408;
                    unsigned sW = sb + SW + bi*17408;
                    unsigned wB = sW + (ngA*8 + (lane&7))*272 + ((lane>>3)&3)*16 + ksA*128;
                    unsigned bh[8], bl[8];
                    ldm4(bh[0],bh[1],bh[2],bh[3], wB);
                    ldm4(bh[4],bh[5],bh[6],bh[7], wB + 64);
                    ldm4(bl[0],bl[1],bl[2],bl[3], wB + 8704);
                    ldm4(bl[4],bl[5],bl[6],bl[7], wB + 8704 + 64);
                    unsigned aB = sA + (lane&15)*272 + ((lane>>4)&1)*16 + ksA*128;
                    #pragma unroll
                    for (int s=0;s<4;s++){
                        unsigned a0[4], a1[4], l0[4], l1[4];
                        ldm4(a0[0],a0[1],a0[2],a0[3], aB + s*32);
                        ldm4(a1[0],a1[1],a1[2],a1[3], aB + 16*272 + s*32);
                        ldm4(l0[0],l0[1],l0[2],l0[3], aB + 8704 + s*32);
                        ldm4(l1[0],l1[1],l1[2],l1[3], aB + 8704 + 16*272 + s*32);
                        mma16816(c0[0], a0, bh+2*s); mma16816(c0[1], a1, bh+2*s);
                        mma16816(c1[0], a0, bl+2*s); mma16816(c1[1], a1, bl+2*s);
                        mma16816(c2[0], l0, bh+2*s); mma16816(c2[1], l1, bh+2*s);
                    }
                }
            }
            __syncthreads();
            #pragma unroll
            for (int fm=0;fm<2;fm++)
                #pragma unroll
                for (int q=0;q<4;q++){
                    int m = fm*16 + (lane>>2) + (q>>1)*8;
                    int nl = (lane&3)*2 + (q&1);
                    redf[((ksA*4+ngA)*32 + m)*8 + nl] = c0[fm][q]+c1[fm][q]+c2[fm][q];
                }
            __syncthreads();
            #pragma unroll
            for (int u=0;u<4;u++){
                int o = tid + u*NTHR;
                int m = o>>5, col = o&31;
                int ng2 = col>>3, nl = col&7;
                float s = redf[(ng2*32+m)*8+nl] + redf[((4+ng2)*32+m)*8+nl];
                if (col < 16){
                    if (do0){
                        int n = c*16 + col;
                        s += g_gx0[((size_t)t*BB+m)*H2 + n] + bg0[n];
                        float g = sigf(s);
                        if (n < H){
                            float v = g * g_h0m[cur][m*H+n];
                            wsplit(v, g_rh0h, g_rh0l, (size_t)m*H + n);
                        } else g_u0m[m*H + n-H] = g;
                    }
                } else {
                    if (do1){
                        int n = c*16 + col - 16;
                        s += bg1[n];
                        float g = sigf(s);
                        if (n < H){
                            float v = g * g_h1m[m*H+n];
                            wsplit(v, g_rh1h, g_rh1l, (size_t)m*H + n);
                        } else g_u1m[m*H + n-H] = g;
                    }
                }
            }
        }
        gsync();

        // ===================== PHASE B: candidates + update =====================
        {
            auto stage = [&](int kc){
                int bi = kc & 3;
                char* A1b = smc + SA1 + bi*17408;
                const bf16 *sh, *sl; int ko;
                if (kc < 8){ sh = g_h0h[cur]; sl = g_h0l[cur]; ko = kc*128; }
                else       { sh = g_rh1h;     sl = g_rh1l;     ko = (kc-8)*128; }
                #pragma unroll
                for (int u=0;u<2;u++){
                    int e = tid + u*NTHR; int row = e>>4, g = e&15;
                    cp16(A1b + row*272 + g*16,        sh + (size_t)row*H + ko + g*8);
                    cp16(A1b + 8704 + row*272 + g*16, sl + (size_t)row*H + ko + g*8);
                }
                if (kc < 8){
                    char* A0b = smc + SA + bi*17408;
                    #pragma unroll
                    for (int u=0;u<2;u++){
                        int e = tid + u*NTHR; int row = e>>4, g = e&15;
                        cp16(A0b + row*272 + g*16,        g_rh0h + (size_t)row*H + kc*128 + g*8);
                        cp16(A0b + 8704 + row*272 + g*16, g_rh0l + (size_t)row*H + kc*128 + g*8);
                    }
                }
                char* Wb = smc + SW + bi*17408;
                {   int pl = tid>>7, i = tid&127, r = i>>4, g = i&15;
                    size_t o1 = (size_t)(c*8 + r)*H2 + kc*128 + g*8;
                    cp16(Wb + pl*8704 + (8+r)*272 + g*16, (pl? g_wct1l : g_wct1h) + o1);
                    if (kc < 8){
                        size_t o0 = (size_t)(c*8 + r)*H + kc*128 + g*8;
                        cp16(Wb + pl*8704 + r*272 + g*16, (pl? g_wct0l : g_wct0h) + o0);
                    }
                }
                CP_COMMIT;
            };
            stage(0); stage(1); stage(2);
            float c0[2][4], c1[2][4], c2[2][4];
            #pragma unroll
            for (int fm=0;fm<2;fm++)
                #pragma unroll
                for (int q=0;q<4;q++){ c0[fm][q]=0.f; c1[fm][q]=0.f; c2[fm][q]=0.f; }

            for (int kc=0;kc<nc;kc++){
                cp_wait_rem(nc-1-kc);
                __syncthreads();
                if (kc+3 < nc) stage(kc+3);
                const bool act = (lB == 0) ? (do0 && kc < 8) : do1;
                if (act){
                    int bi = kc & 3;
                    unsigned sAx = sb + (lB ? SA1 : SA) + bi*17408;
                    unsigned sW = sb + SW + bi*17408;
                    unsigned wB = sW + (lB*8 + (lane&7))*272 + ((lane>>3)&3)*16 + ksB*64;
                    unsigned bh[4], bl[4];
                    ldm4(bh[0],bh[1],bh[2],bh[3], wB);
                    ldm4(bl[0],bl[1],bl[2],bl[3], wB + 8704);
                    unsigned aB = sAx + (lane&15)*272 + ((lane>>4)&1)*16 + ksB*64;
                    #pragma unroll
                    for (int s=0;s<2;s++){
                        unsigned a0[4], a1[4], l0[4], l1[4];
                        ldm4(a0[0],a0[1],a0[2],a0[3], aB + s*32);
                        ldm4(a1[0],a1[1],a1[2],a1[3], aB + 16*272 + s*32);
                        ldm4(l0[0],l0[1],l0[2],l0[3], aB + 8704 + s*32);
                        ldm4(l1[0],l1[1],l1[2],l1[3], aB + 8704 + 16*272 + s*32);
                        mma16816(c0[0], a0, bh+2*s); mma16816(c0[1], a1, bh+2*s);
                        mma16816(c1[0], a0, bl+2*s); mma16816(c1[1], a1, bl+2*s);
                        mma16816(c2[0], l0, bh+2*s); mma16816(c2[1], l1, bh+2*s);
                    }
                }
            }
            __syncthreads();
            #pragma unroll
            for (int fm=0;fm<2;fm++)
                #pragma unroll
                for (int q=0;q<4;q++){
                    int m = fm*16 + (lane>>2) + (q>>1)*8;
                    int nl = (lane&3)*2 + (q&1);
                    redf[((ksB*2+lB)*32 + m)*8 + nl] = c0[fm][q]+c1[fm][q]+c2[fm][q];
                }
            __syncthreads();
            #pragma unroll
            for (int u=0;u<2;u++){
                int o = tid + u*NTHR;
                int m = o>>4, col = o&15;
                int lg = col>>3, nl = col&7;
                float s = redf[((0*2+lg)*32+m)*8+nl] + redf[((1*2+lg)*32+m)*8+nl]
                        + redf[((2*2+lg)*32+m)*8+nl] + redf[((3*2+lg)*32+m)*8+nl];
                if (lg == 0){
                    if (do0){
                        int n = c*8 + nl;
                        s += g_cx0[((size_t)t*BB+m)*H + n] + bc0[n];
                        float cc = tanhx(s);
                        float uu = g_u0m[m*H+n];
                        float hn = uu * g_h0m[cur][m*H+n] + (1.f-uu)*cc;
                        g_h0m[cur^1][m*H+n] = hn;
                        wsplit(hn, g_h0h[cur^1], g_h0l[cur^1], (size_t)m*H + n);
                    }
                } else {
                    if (do1){
                        int n = c*8 + nl;
                        s += bc1[n];
                        float cc = tanhx(s);
                        float uu = g_u1m[m*H+n];
                        float hn = uu * g_h1m[m*H+n] + (1.f-uu)*cc;
                        g_h1m[m*H+n] = hn;
                        wsplit(hn, g_h1h, g_h1l, (size_t)m*H + n);
                        g_outT[((size_t)(t-1)*BB+m)*H + n] = hn;
                    }
                }
            }
        }
        cur ^= 1;
        gsync();
    }
}

// ---------------- launch ----------------
extern "C" void kernel_launch(void* const* d_in, const int* in_sizes, int n_in,
                              void* d_out, int out_size)
{
    const int*   idx = (const int*)  d_in[0];
    const float* emb = (const float*)d_in[1];
    const float* Wg0 = (const float*)d_in[2];
    const float* bg0 = (const float*)d_in[3];
    const float* Wc0 = (const float*)d_in[4];
    const float* bc0 = (const float*)d_in[5];
    const float* Wg1 = (const float*)d_in[6];
    const float* bg1 = (const float*)d_in[7];
    const float* Wc1 = (const float*)d_in[8];
    const float* bc1 = (const float*)d_in[9];
    const float* smb = (const float*)d_in[10];
    float* out = (float*)d_out;

    float *pgx0,*pcx0,*poutT;
    bf16 *pxh,*pxl,*poh,*pol,*pwgh,*pwgl,*pwch,*pwcl,*peh,*pel;
    cudaGetSymbolAddress((void**)&pgx0,  g_gx0);
    cudaGetSymbolAddress((void**)&pcx0,  g_cx0);
    cudaGetSymbolAddress((void**)&poutT, g_outT);
    cudaGetSymbolAddress((void**)&pxh,   g_xh);
    cudaGetSymbolAddress((void**)&pxl,   g_xl);
    cudaGetSymbolAddress((void**)&poh,   g_oh);
    cudaGetSymbolAddress((void**)&pol,   g_ol);
    cudaGetSymbolAddress((void**)&pwgh,  g_wgh);
    cudaGetSymbolAddress((void**)&pwgl,  g_wgl);
    cudaGetSymbolAddress((void**)&pwch,  g_wch);
    cudaGetSymbolAddress((void**)&pwcl,  g_wcl);
    cudaGetSymbolAddress((void**)&peh,   g_eh);
    cudaGetSymbolAddress((void**)&pel,   g_el);

    static bool attr_set = false;
    if (!attr_set){
        cudaFuncSetAttribute(rnn_persist, cudaFuncAttributeMaxDynamicSharedMemorySize, RSM);
        cudaFuncSetAttribute(hgemm<true>,  cudaFuncAttributeMaxDynamicSharedMemorySize, HSM);
        cudaFuncSetAttribute(hgemm<false>, cudaFuncAttributeMaxDynamicSharedMemorySize, HSM);
        attr_set = true;
    }

    prep_wq<<<9216, 256>>>(Wg0, Wg1, Wc0, Wc1);
    prep_cv<<<7168 + VPAD, 256>>>(idx, emb, Wg0, Wc0);

    hgemm<true><<<dim3(H2/64, MROWS/128), 256, HSM>>>(pxh, pxl, pwgh, pwgl, nullptr, pgx0, H2);
    hgemm<true><<<dim3(H/64,  MROWS/128), 256, HSM>>>(pxh, pxl, pwch, pwcl, nullptr, pcx0, H);

    rnn_persist<<<NB, NTHR, RSM>>>(bg0, bc0, bg1, bc1);

    outconv<<<MROWS, 256>>>(poutT);
    hgemm<false><<<dim3(VPAD/64, MROWS/128), 256, HSM>>>(poh, pol, peh, pel, smb, out, VOCAB);
}

// round 14
// speedup vs baseline: 1.4257x; 1.0150x over previous
#include <cuda_runtime.h>
#include <cuda_bf16.h>
#include <math.h>
typedef unsigned long long ull;
typedef __nv_bfloat16 bf16;

#define VOCAB 10000
#define VPAD  10048
#define H 1024
#define H2 2048
#define BB 32
#define TT 128
#define MROWS (BB*TT)
#define NB 128
#define NTHR 256

// rnn smem (bytes): chunk=256 bf16; plane = 32 rows x 528B = 16896; buf(hi+lo)=33792
#define BUFB 33792
#define PLB  16896
#define SA   0
#define SA1  67584
#define SW   135168
#define SRED 202752
#define RSM  210944

// hgemm smem (bytes)
#define HA_L 18432
#define HB_H 36864
#define HB_L 46080
#define HBUF 55296
#define HSM  (2*HBUF)

// ---------------- device scratch ----------------
__device__ __align__(16) float g_gx0[(size_t)TT*BB*H2];   // [t][m][n]
__device__ __align__(16) float g_cx0[(size_t)TT*BB*H];
__device__ __align__(16) float g_outT[(size_t)TT*BB*H];
__device__ __align__(16) float g_h0m[2][BB*H];
__device__ __align__(16) float g_h1m[BB*H];
__device__ __align__(16) float g_u0m[BB*H];
__device__ __align__(16) float g_u1m[BB*H];
__device__ __align__(16) bf16 g_h0h[2][BB*H], g_h0l[2][BB*H];
__device__ __align__(16) bf16 g_h1h[BB*H],  g_h1l[BB*H];
__device__ __align__(16) bf16 g_rh0h[BB*H], g_rh0l[BB*H];
__device__ __align__(16) bf16 g_rh1h[BB*H], g_rh1l[BB*H];
__device__ __align__(16) bf16 g_wgt0h[(size_t)H2*H],  g_wgt0l[(size_t)H2*H];
__device__ __align__(16) bf16 g_wgt1h[(size_t)H2*H2], g_wgt1l[(size_t)H2*H2];
__device__ __align__(16) bf16 g_wct0h[(size_t)H*H],   g_wct0l[(size_t)H*H];
__device__ __align__(16) bf16 g_wct1h[(size_t)H*H2],  g_wct1l[(size_t)H*H2];
__device__ __align__(16) bf16 g_xh[(size_t)MROWS*H], g_xl[(size_t)MROWS*H];
__device__ __align__(16) bf16 g_oh[(size_t)MROWS*H], g_ol[(size_t)MROWS*H];
__device__ __align__(16) bf16 g_wgh[(size_t)H2*H],  g_wgl[(size_t)H2*H];
__device__ __align__(16) bf16 g_wch[(size_t)H*H],   g_wcl[(size_t)H*H];
__device__ __align__(16) bf16 g_eh[(size_t)VPAD*H], g_el[(size_t)VPAD*H];
__device__ volatile unsigned g_cnt;
__device__ volatile unsigned g_gen;

// ---------------- helpers ----------------
__device__ __forceinline__ float sigf(float x){ return __fdividef(1.f, 1.f+__expf(-x)); }
__device__ __forceinline__ float tanhx(float x){ return 1.f-__fdividef(2.f, __expf(2.f*x)+1.f); }

__device__ __forceinline__ void cp16(void* d, const void* s){
    unsigned ds = (unsigned)__cvta_generic_to_shared(d);
    asm volatile("cp.async.cg.shared.global [%0], [%1], 16;" :: "r"(ds), "l"(s) : "memory");
}
#define CP_COMMIT asm volatile("cp.async.commit_group;" ::: "memory")
#define CP_WAIT0  asm volatile("cp.async.wait_group 0;" ::: "memory")
#define CP_WAIT1  asm volatile("cp.async.wait_group 1;" ::: "memory")

__device__ __forceinline__ void gsync(){
    __threadfence();
    __syncthreads();
    if (threadIdx.x == 0){
        unsigned gen = g_gen;
        unsigned old = atomicAdd((unsigned*)&g_cnt, 1u);
        if (old == NB-1){ g_cnt = 0; __threadfence(); g_gen = gen+1; }
        else { while (g_gen == gen) { __nanosleep(40); } }
    }
    __syncthreads();
}

__device__ __forceinline__ void ldm4(unsigned& r0, unsigned& r1, unsigned& r2, unsigned& r3,
                                     unsigned addr){
    asm volatile("ldmatrix.sync.aligned.m8n8.x4.shared.b16 {%0,%1,%2,%3}, [%4];"
        : "=r"(r0), "=r"(r1), "=r"(r2), "=r"(r3) : "r"(addr));
}
__device__ __forceinline__ void mma16816(float* c, const unsigned* a, const unsigned* b){
    asm volatile("mma.sync.aligned.m16n8k16.row.col.f32.bf16.bf16.f32 "
        "{%0,%1,%2,%3},{%4,%5,%6,%7},{%8,%9},{%0,%1,%2,%3};"
        : "+f"(c[0]), "+f"(c[1]), "+f"(c[2]), "+f"(c[3])
        : "r"(a[0]), "r"(a[1]), "r"(a[2]), "r"(a[3]), "r"(b[0]), "r"(b[1]));
}
__device__ __forceinline__ void wsplit(float v, bf16* hp, bf16* lp, size_t o){
    bf16 h = __float2bfloat16(v);
    hp[o] = h; lp[o] = __float2bfloat16(v - __bfloat162float(h));
}

// ---------------- prep kernels ----------------
__global__ void prep_wq(const float* __restrict__ Wg0, const float* __restrict__ Wg1,
                        const float* __restrict__ Wc0, const float* __restrict__ Wc1){
    __shared__ float s[32][33];
    int b = blockIdx.x;
    const float* src; bf16 *dh, *dl; int srow0, ld, ldd, bx, by;
    if (b < 2048){      src=Wg0; srow0=1024; ld=H2; dh=g_wgt0h; dl=g_wgt0l; ldd=H;  bx=b&31; by=b>>5; }
    else if (b<6144){ int q=b-2048; src=Wg1; srow0=0; ld=H2; dh=g_wgt1h; dl=g_wgt1l; ldd=H2; bx=q&63; by=q>>6; }
    else if (b<7168){ int q=b-6144; src=Wc0; srow0=1024; ld=H; dh=g_wct0h; dl=g_wct0l; ldd=H; bx=q&31; by=q>>5; }
    else {            int q=b-7168; src=Wc1; srow0=0; ld=H; dh=g_wct1h; dl=g_wct1l; ldd=H2; bx=q&63; by=q>>6; }
    int kb = bx*32, nb = by*32;
    int t = threadIdx.x, tx = t&31, ty = t>>5;
#pragma unroll
    for (int i=0;i<32;i+=8) s[ty+i][tx] = src[(size_t)(srow0+kb+ty+i)*ld + nb+tx];
    __syncthreads();
#pragma unroll
    for (int i=0;i<32;i+=8)
        wsplit(s[tx][ty+i], dh, dl, (size_t)(nb+ty+i)*ldd + kb+tx);
}

__global__ void prep_cv(const int* __restrict__ idx, const float* __restrict__ emb,
                        const float* __restrict__ Wg0, const float* __restrict__ Wc0){
    __shared__ float s[32][33];
    int b = blockIdx.x, t = threadIdx.x;
    if (b < 4096){
        float4 v = ((const float4*)(emb + (size_t)idx[b]*H))[t];
        float a[4] = {v.x,v.y,v.z,v.w};
        size_t o = (size_t)b*H + t*4;
#pragma unroll
        for (int j=0;j<4;j++) wsplit(a[j], g_xh, g_xl, o+j);
    } else if (b < 7168){
        const float* src; bf16 *hi, *lo; int ld, kb, nb;
        if (b < 6144){ int q=b-4096; src=Wg0; ld=H2; hi=g_wgh; lo=g_wgl; kb=(q&31)*32; nb=(q>>5)*32; }
        else         { int q=b-6144; src=Wc0; ld=H;  hi=g_wch; lo=g_wcl; kb=(q&31)*32; nb=(q>>5)*32; }
        int tx = t&31, ty = t>>5;
#pragma unroll
        for (int i=0;i<32;i+=8) s[ty+i][tx] = src[(size_t)(kb+ty+i)*ld + nb+tx];
        __syncthreads();
#pragma unroll
        for (int i=0;i<32;i+=8)
            wsplit(s[tx][ty+i], hi, lo, (size_t)(nb+ty+i)*H + kb+tx);
    } else {
        int row = b - 7168;
        size_t o = (size_t)row*H + t*4;
        if (row < VOCAB){
            float4 v = ((const float4*)(emb + (size_t)row*H))[t];
            float a[4] = {v.x,v.y,v.z,v.w};
#pragma unroll
            for (int j=0;j<4;j++) wsplit(a[j], g_eh, g_el, o+j);
        } else {
#pragma unroll
            for (int j=0;j<4;j++){ g_eh[o+j]=__float2bfloat16(0.f); g_el[o+j]=__float2bfloat16(0.f); }
        }
    }
}

__global__ void outconv(const float* __restrict__ outT){
    int r = blockIdx.x, tid = threadIdx.x;
    int m = r>>7, t = r&127;
    float4 v = ((const float4*)(outT + ((size_t)t*BB + m)*H))[tid];
    float a[4] = {v.x,v.y,v.z,v.w};
    size_t o = (size_t)r*H + tid*4;
#pragma unroll
    for (int j=0;j<4;j++) wsplit(a[j], g_oh, g_ol, o+j);
}

// ---------------- HMMA bf16-split big GEMM (r13, proven) ----------------
template<bool GRUL>
__global__ void __launch_bounds__(256, 2)
hgemm(const bf16* __restrict__ Ah, const bf16* __restrict__ Al,
      const bf16* __restrict__ Bh, const bf16* __restrict__ Bl,
      const float* __restrict__ bias, float* __restrict__ C, int N)
{
    extern __shared__ __align__(16) char smc[];
    const int tid = threadIdx.x, wid = tid>>5, lane = tid&31;
    const int n0 = blockIdx.x*64, m0 = blockIdx.y*128;
    const int wm = wid&3, wn = wid>>2;
    unsigned sb = (unsigned)__cvta_generic_to_shared(smc);

    auto stage = [&](int kc){
        char* base = smc + (kc&1)*HBUF;
#pragma unroll
        for (int u=0;u<8;u++){
            int e = tid + u*256;
            int pl = e>>10, i = e&1023, row = i>>3, g = i&7;
            const bf16* src = (pl?Al:Ah) + (size_t)(m0+row)*H + kc*64 + g*8;
            cp16(base + (pl?HA_L:0) + row*144 + g*16, src);
        }
#pragma unroll
        for (int u=0;u<4;u++){
            int e = tid + u*256;
            int pl = e>>9, i = e&511, row = i>>3, g = i&7;
            const bf16* src = (pl?Bl:Bh) + (size_t)(n0+row)*H + kc*64 + g*8;
            cp16(base + (pl?HB_L:HB_H) + row*144 + g*16, src);
        }
    };

    float cc[2][4][4];
#pragma unroll
    for (int a=0;a<2;a++)
#pragma unroll
        for (int b=0;b<4;b++)
#pragma unroll
            for (int q=0;q<4;q++) cc[a][b][q] = 0.f;

    stage(0); CP_COMMIT;
    for (int kc=0;kc<16;kc++){
        if (kc < 15){ stage(kc+1); CP_COMMIT; CP_WAIT1; } else CP_WAIT0;
        __syncthreads();
        unsigned bufb = sb + (kc&1)*HBUF;
        unsigned aB = bufb + (wm*32 + (lane&15))*144 + ((lane>>4)&1)*16;
        unsigned bB = bufb + HB_H + (wn*32 + (lane&7) + ((lane>>4)&1)*8)*144 + ((lane>>3)&1)*16;
#pragma unroll
        for (int ks=0;ks<4;ks++){
            unsigned ah[8], al[8], bh[8], bl[8];
            ldm4(ah[0],ah[1],ah[2],ah[3], aB + ks*32);
            ldm4(ah[4],ah[5],ah[6],ah[7], aB + 16*144 + ks*32);
            ldm4(al[0],al[1],al[2],al[3], aB + HA_L + ks*32);
            ldm4(al[4],al[5],al[6],al[7], aB + HA_L + 16*144 + ks*32);
            ldm4(bh[0],bh[1],bh[2],bh[3], bB + ks*32);
            ldm4(bh[4],bh[5],bh[6],bh[7], bB + 16*144 + ks*32);
            ldm4(bl[0],bl[1],bl[2],bl[3], bB + (HB_L-HB_H) + ks*32);
            ldm4(bl[4],bl[5],bl[6],bl[7], bB + (HB_L-HB_H) + 16*144 + ks*32);
#pragma unroll
            for (int fm=0;fm<2;fm++)
#pragma unroll
                for (int fn=0;fn<4;fn++){
                    mma16816(cc[fm][fn], ah+fm*4, bh+fn*2);
                    mma16816(cc[fm][fn], ah+fm*4, bl+fn*2);
                    mma16816(cc[fm][fn], al+fm*4, bh+fn*2);
                }
        }
        __syncthreads();
    }

    const int rb = lane>>2, cb = (lane&3)*2;
#pragma unroll
    for (int fm=0;fm<2;fm++){
#pragma unroll
        for (int half=0;half<2;half++){
            int r = m0 + wm*32 + fm*16 + rb + half*8;
            int r2 = GRUL ? ((r & 127)*BB + (r >> 7)) : r;
            float* crow = C + (size_t)r2*N;
#pragma unroll
            for (int fn=0;fn<4;fn++){
                int n = n0 + wn*32 + fn*8 + cb;
                if (n < N){
                    float2 v;
                    v.x = cc[fm][fn][half*2+0];
                    v.y = cc[fm][fn][half*2+1];
                    if (bias){
                        float2 b = *(const float2*)(bias + n);
                        v.x += b.x; v.y += b.y;
                    }
                    *(float2*)(crow + n) = v;
                }
            }
        }
    }
}

// ---------------- persistent HMMA recurrence (chunk=256, ring-2) ----------------
__global__ void __launch_bounds__(NTHR, 1)
rnn_persist(const float* __restrict__ bg0, const float* __restrict__ bc0,
            const float* __restrict__ bg1, const float* __restrict__ bc1)
{
    extern __shared__ __align__(16) char smc[];
    const int tid = threadIdx.x, c = blockIdx.x;
    const int lane = tid & 31, w = tid >> 5;
    unsigned sb = (unsigned)__cvta_generic_to_shared(smc);
    float* redf = (float*)(smc + SRED);

    {   int gt = c*NTHR + tid;
        bf16 z = __float2bfloat16(0.f);
        g_h0m[0][gt]=0.f; g_h1m[gt]=0.f;
        g_h0h[0][gt]=z; g_h0l[0][gt]=z; g_h1h[gt]=z; g_h1l[gt]=z;
    }
    gsync();

    const int ngA = w & 3, ksA = w >> 2;   // 4 n-groups x 2 k-split (128 k each)
    const int lB = w & 1, ksB = w >> 1;    // 2 layers x 4 k-split (64 k each)

    int cur = 0;
    for (int t = 0; t <= TT; t++){
        const bool do0 = (t < TT), do1 = (t > 0);
        const int nc = do1 ? 8 : 4;

        // ===================== PHASE A: gates =====================
        {
            auto stage = [&](int kc){
                int bi = kc & 1;
                char* Ab = smc + SA + bi*BUFB;
                const bf16 *sh, *sl; int ko;
                if (kc < 4){ sh = g_h0h[cur]; sl = g_h0l[cur]; ko = kc*256; }
                else       { sh = g_h1h;      sl = g_h1l;      ko = (kc-4)*256; }
                #pragma unroll
                for (int u=0;u<8;u++){
                    int e = tid + u*NTHR; int pl = e>>10, i = e&1023, row = i>>5, g = i&31;
                    cp16(Ab + pl*PLB + row*528 + g*16, (pl?sl:sh) + (size_t)row*H + ko + g*8);
                }
                char* Wb = smc + SW + bi*BUFB;
                #pragma unroll
                for (int u=0;u<4;u++){
                    int e = tid + u*NTHR; int pl = e>>9, i = e&511, r = i>>5, g = i&31;
                    size_t o1 = (size_t)(c*16 + r)*H2 + kc*256 + g*8;
                    cp16(Wb + pl*PLB + (16+r)*528 + g*16, (pl?g_wgt1l:g_wgt1h) + o1);
                }
                if (kc < 4){
                    #pragma unroll
                    for (int u=0;u<4;u++){
                        int e = tid + u*NTHR; int pl = e>>9, i = e&511, r = i>>5, g = i&31;
                        size_t o0 = (size_t)(c*16 + r)*H + kc*256 + g*8;
                        cp16(Wb + pl*PLB + r*528 + g*16, (pl?g_wgt0l:g_wgt0h) + o0);
                    }
                }
                CP_COMMIT;
            };
            stage(0);
            float c0[2][4], c1[2][4], c2[2][4];
            #pragma unroll
            for (int fm=0;fm<2;fm++)
                #pragma unroll
                for (int q=0;q<4;q++){ c0[fm][q]=0.f; c1[fm][q]=0.f; c2[fm][q]=0.f; }

            for (int kc=0;kc<nc;kc++){
                CP_WAIT0;
                __syncthreads();
                if (kc+1 < nc) stage(kc+1);
                const bool act = (ngA < 2) ? (do0 && kc < 4) : do1;
                if (act){
                    int bi = kc & 1;
                    unsigned sA = sb + SA + bi*BUFB;
                    unsigned sW = sb + SW + bi*BUFB;
                    unsigned wB = sW + (ngA*8 + (lane&7))*528 + ((lane>>3)&3)*16 + ksA*256;
                    unsigned bh[16], bl[16];
                    ldm4(bh[0],bh[1],bh[2],bh[3],   wB);
                    ldm4(bh[4],bh[5],bh[6],bh[7],   wB + 64);
                    ldm4(bh[8],bh[9],bh[10],bh[11], wB + 128);
                    ldm4(bh[12],bh[13],bh[14],bh[15], wB + 192);
                    ldm4(bl[0],bl[1],bl[2],bl[3],   wB + PLB);
                    ldm4(bl[4],bl[5],bl[6],bl[7],   wB + PLB + 64);
                    ldm4(bl[8],bl[9],bl[10],bl[11], wB + PLB + 128);
                    ldm4(bl[12],bl[13],bl[14],bl[15], wB + PLB + 192);
                    unsigned aB = sA + (lane&15)*528 + ((lane>>4)&1)*16 + ksA*256;
                    #pragma unroll
                    for (int s=0;s<8;s++){
                        unsigned a0[4], a1[4], l0[4], l1[4];
                        ldm4(a0[0],a0[1],a0[2],a0[3], aB + s*32);
                        ldm4(a1[0],a1[1],a1[2],a1[3], aB + 16*528 + s*32);
                        ldm4(l0[0],l0[1],l0[2],l0[3], aB + PLB + s*32);
                        ldm4(l1[0],l1[1],l1[2],l1[3], aB + PLB + 16*528 + s*32);
                        mma16816(c0[0], a0, bh+2*s); mma16816(c0[1], a1, bh+2*s);
                        mma16816(c1[0], a0, bl+2*s); mma16816(c1[1], a1, bl+2*s);
                        mma16816(c2[0], l0, bh+2*s); mma16816(c2[1], l1, bh+2*s);
                    }
                }
            }
            __syncthreads();
            #pragma unroll
            for (int fm=0;fm<2;fm++)
                #pragma unroll
                for (int q=0;q<4;q++){
                    int m = fm*16 + (lane>>2) + (q>>1)*8;
                    int nl = (lane&3)*2 + (q&1);
                    redf[((ksA*4+ngA)*32 + m)*8 + nl] = c0[fm][q]+c1[fm][q]+c2[fm][q];
                }
            __syncthreads();
            #pragma unroll
            for (int u=0;u<4;u++){
                int o = tid + u*NTHR;
                int m = o>>5, col = o&31;
                int ng2 = col>>3, nl = col&7;
                float s = redf[(ng2*32+m)*8+nl] + redf[((4+ng2)*32+m)*8+nl];
                if (col < 16){
                    if (do0){
                        int n = c*16 + col;
                        s += g_gx0[((size_t)t*BB+m)*H2 + n] + bg0[n];
                        float g = sigf(s);
                        if (n < H){
                            float v = g * g_h0m[cur][m*H+n];
                            wsplit(v, g_rh0h, g_rh0l, (size_t)m*H + n);
                        } else g_u0m[m*H + n-H] = g;
                    }
                } else {
                    if (do1){
                        int n = c*16 + col - 16;
                        s += bg1[n];
                        float g = sigf(s);
                        if (n < H){
                            float v = g * g_h1m[m*H+n];
                            wsplit(v, g_rh1h, g_rh1l, (size_t)m*H + n);
                        } else g_u1m[m*H + n-H] = g;
                    }
                }
            }
        }
        gsync();

        // ===================== PHASE B: candidates + update =====================
        {
            auto stage = [&](int kc){
                int bi = kc & 1;
                char* A1b = smc + SA1 + bi*BUFB;
                const bf16 *sh, *sl; int ko;
                if (kc < 4){ sh = g_h0h[cur]; sl = g_h0l[cur]; ko = kc*256; }
                else       { sh = g_rh1h;     sl = g_rh1l;     ko = (kc-4)*256; }
                #pragma unroll
                for (int u=0;u<8;u++){
                    int e = tid + u*NTHR; int pl = e>>10, i = e&1023, row = i>>5, g = i&31;
                    cp16(A1b + pl*PLB + row*528 + g*16, (pl?sl:sh) + (size_t)row*H + ko + g*8);
                }
                if (kc < 4){
                    char* A0b = smc + SA + bi*BUFB;
                    #pragma unroll
                    for (int u=0;u<8;u++){
                        int e = tid + u*NTHR; int pl = e>>10, i = e&1023, row = i>>5, g = i&31;
                        cp16(A0b + pl*PLB + row*528 + g*16,
                             (pl?g_rh0l:g_rh0h) + (size_t)row*H + kc*256 + g*8);
                    }
                }
                char* Wb = smc + SW + bi*BUFB;
                #pragma unroll
                for (int u=0;u<2;u++){
                    int e = tid + u*NTHR; int pl = e>>8, i = e&255, r = i>>5, g = i&31;
                    size_t o1 = (size_t)(c*8 + r)*H2 + kc*256 + g*8;
                    cp16(Wb + pl*PLB + (8+r)*528 + g*16, (pl?g_wct1l:g_wct1h) + o1);
                }
                if (kc < 4){
                    #pragma unroll
                    for (int u=0;u<2;u++){
                        int e = tid + u*NTHR; int pl = e>>8, i = e&255, r = i>>5, g = i&31;
                        size_t o0 = (size_t)(c*8 + r)*H + kc*256 + g*8;
                        cp16(Wb + pl*PLB + r*528 + g*16, (pl?g_wct0l:g_wct0h) + o0);
                    }
                }
                CP_COMMIT;
            };
            stage(0);
            float c0[2][4], c1[2][4], c2[2][4];
            #pragma unroll
            for (int fm=0;fm<2;fm++)
                #pragma unroll
                for (int q=0;q<4;q++){ c0[fm][q]=0.f; c1[fm][q]=0.f; c2[fm][q]=0.f; }

            for (int kc=0;kc<nc;kc++){
                CP_WAIT0;
                __syncthreads();
                if (kc+1 < nc) stage(kc+1);
                const bool act = (lB == 0) ? (do0 && kc < 4) : do1;
                if (act){
                    int bi = kc & 1;
                    unsigned sAx = sb + (lB ? SA1 : SA) + bi*BUFB;
                    unsigned sW = sb + SW + bi*BUFB;
                    unsigned wB = sW + (lB*8 + (lane&7))*528 + ((lane>>3)&3)*16 + ksB*128;
                    unsigned bh[8], bl[8];
                    ldm4(bh[0],bh[1],bh[2],bh[3], wB);
                    ldm4(bh[4],bh[5],bh[6],bh[7], wB + 64);
                    ldm4(bl[0],bl[1],bl[2],bl[3], wB + PLB);
                    ldm4(bl[4],bl[5],bl[6],bl[7], wB + PLB + 64);
                    unsigned aB = sAx + (lane&15)*528 + ((lane>>4)&1)*16 + ksB*128;
                    #pragma unroll
                    for (int s=0;s<4;s++){
                        unsigned a0[4], a1[4], l0[4], l1[4];
                        ldm4(a0[0],a0[1],a0[2],a0[3], aB + s*32);
                        ldm4(a1[0],a1[1],a1[2],a1[3], aB + 16*528 + s*32);
                        ldm4(l0[0],l0[1],l0[2],l0[3], aB + PLB + s*32);
                        ldm4(l1[0],l1[1],l1[2],l1[3], aB + PLB + 16*528 + s*32);
                        mma16816(c0[0], a0, bh+2*s); mma16816(c0[1], a1, bh+2*s);
                        mma16816(c1[0], a0, bl+2*s); mma16816(c1[1], a1, bl+2*s);
                        mma16816(c2[0], l0, bh+2*s); mma16816(c2[1], l1, bh+2*s);
                    }
                }
            }
            __syncthreads();
            #pragma unroll
            for (int fm=0;fm<2;fm++)
                #pragma unroll
                for (int q=0;q<4;q++){
                    int m = fm*16 + (lane>>2) + (q>>1)*8;
                    int nl = (lane&3)*2 + (q&1);
                    redf[((ksB*2+lB)*32 + m)*8 + nl] = c0[fm][q]+c1[fm][q]+c2[fm][q];
                }
            __syncthreads();
            #pragma unroll
            for (int u=0;u<2;u++){
                int o = tid + u*NTHR;
                int m = o>>4, col = o&15;
                int lg = col>>3, nl = col&7;
                float s = redf[((0*2+lg)*32+m)*8+nl] + redf[((1*2+lg)*32+m)*8+nl]
                        + redf[((2*2+lg)*32+m)*8+nl] + redf[((3*2+lg)*32+m)*8+nl];
                if (lg == 0){
                    if (do0){
                        int n = c*8 + nl;
                        s += g_cx0[((size_t)t*BB+m)*H + n] + bc0[n];
                        float cc = tanhx(s);
                        float uu = g_u0m[m*H+n];
                        float hn = uu * g_h0m[cur][m*H+n] + (1.f-uu)*cc;
                        g_h0m[cur^1][m*H+n] = hn;
                        wsplit(hn, g_h0h[cur^1], g_h0l[cur^1], (size_t)m*H + n);
                    }
                } else {
                    if (do1){
                        int n = c*8 + nl;
                        s += bc1[n];
                        float cc = tanhx(s);
                        float uu = g_u1m[m*H+n];
                        float hn = uu * g_h1m[m*H+n] + (1.f-uu)*cc;
                        g_h1m[m*H+n] = hn;
                        wsplit(hn, g_h1h, g_h1l, (size_t)m*H + n);
                        g_outT[((size_t)(t-1)*BB+m)*H + n] = hn;
                    }
                }
            }
        }
        cur ^= 1;
        gsync();
    }
}

// ---------------- launch ----------------
extern "C" void kernel_launch(void* const* d_in, const int* in_sizes, int n_in,
                              void* d_out, int out_size)
{
    const int*   idx = (const int*)  d_in[0];
    const float* emb = (const float*)d_in[1];
    const float* Wg0 = (const float*)d_in[2];
    const float* bg0 = (const float*)d_in[3];
    const float* Wc0 = (const float*)d_in[4];
    const float* bc0 = (const float*)d_in[5];
    const float* Wg1 = (const float*)d_in[6];
    const float* bg1 = (const float*)d_in[7];
    const float* Wc1 = (const float*)d_in[8];
    const float* bc1 = (const float*)d_in[9];
    const float* smb = (const float*)d_in[10];
    float* out = (float*)d_out;

    float *pgx0,*pcx0,*poutT;
    bf16 *pxh,*pxl,*poh,*pol,*pwgh,*pwgl,*pwch,*pwcl,*peh,*pel;
    cudaGetSymbolAddress((void**)&pgx0,  g_gx0);
    cudaGetSymbolAddress((void**)&pcx0,  g_cx0);
    cudaGetSymbolAddress((void**)&poutT, g_outT);
    cudaGetSymbolAddress((void**)&pxh,   g_xh);
    cudaGetSymbolAddress((void**)&pxl,   g_xl);
    cudaGetSymbolAddress((void**)&poh,   g_oh);
    cudaGetSymbolAddress((void**)&pol,   g_ol);
    cudaGetSymbolAddress((void**)&pwgh,  g_wgh);
    cudaGetSymbolAddress((void**)&pwgl,  g_wgl);
    cudaGetSymbolAddress((void**)&pwch,  g_wch);
    cudaGetSymbolAddress((void**)&pwcl,  g_wcl);
    cudaGetSymbolAddress((void**)&peh,   g_eh);
    cudaGetSymbolAddress((void**)&pel,   g_el);

    static bool attr_set = false;
    if (!attr_set){
        cudaFuncSetAttribute(rnn_persist, cudaFuncAttributeMaxDynamicSharedMemorySize, RSM);
        cudaFuncSetAttribute(hgemm<true>,  cudaFuncAttributeMaxDynamicSharedMemorySize, HSM);
        cudaFuncSetAttribute(hgemm<false>, cudaFuncAttributeMaxDynamicSharedMemorySize, HSM);
        attr_set = true;
    }

    prep_wq<<<9216, 256>>>(Wg0, Wg1, Wc0, Wc1);
    prep_cv<<<7168 + VPAD, 256>>>(idx, emb, Wg0, Wc0);

    hgemm<true><<<dim3(H2/64, MROWS/128), 256, HSM>>>(pxh, pxl, pwgh, pwgl, nullptr, pgx0, H2);
    hgemm<true><<<dim3(H/64,  MROWS/128), 256, HSM>>>(pxh, pxl, pwch, pwcl, nullptr, pcx0, H);

    rnn_persist<<<NB, NTHR, RSM>>>(bg0, bc0, bg1, bc1);

    outconv<<<MROWS, 256>>>(poutT);
    hgemm<false><<<dim3(VPAD/64, MROWS/128), 256, HSM>>>(poh, pol, peh, pel, smb, out, VOCAB);
}